// round 1
// baseline (speedup 1.0000x reference)
#include <cuda_runtime.h>
#include <math.h>

// ---------------- problem constants ----------------
#define N_B   64
#define C_    64
#define T_    64
#define V_    25
#define NV    (N_B*V_)       // 1600 sequences
#define PLANE (C_*T_)        // 4096 floats per (n,v) plane
#define CTCN  48
#define EPS_  1e-5f

// ---------------- device scratch (no allocations allowed) ----------------
__device__ float g_xT [(size_t)NV*PLANE];   // x transposed: [n][v][c][t]
__device__ float g_peT[(size_t)V_*PLANE];   // pe transposed: [v][c][t]
__device__ float g_sR [(size_t)NV*PLANE];   // result (branches + residual): [n][v][c][t]
__device__ float g_gmul[N_B*C_];            // per-(n,ch) (1+gate)*bn_scale

// ---------------- helpers ----------------
__device__ __forceinline__ unsigned long long ffma2(unsigned long long a,
                                                    unsigned long long b,
                                                    unsigned long long c) {
    unsigned long long d;
    asm("fma.rn.f32x2 %0, %1, %2, %3;" : "=l"(d) : "l"(a), "l"(b), "l"(c));
    return d;
}
__device__ __forceinline__ unsigned long long dup2(float a) {
    unsigned long long r;
    asm("mov.b64 %0, {%1, %1};" : "=l"(r) : "f"(a));
    return r;
}
__device__ __forceinline__ float ftanh(float x) {
    x = fminf(15.f, fmaxf(-15.f, x));
    float e = __expf(2.f * x);
    return __fdividef(e - 1.f, e + 1.f);
}

// ---------------- K0: transpose x and pe into [.. ][c][t] planes ----------------
__global__ void k_transpose(const float* __restrict__ x, const float* __restrict__ pe) {
    __shared__ float buf[T_*V_];
    int b = blockIdx.x;
    const float* src = (b < N_B*C_) ? (x + (size_t)b*(T_*V_))
                                    : (pe + (size_t)(b - N_B*C_)*(T_*V_));
    for (int i = threadIdx.x; i < T_*V_; i += blockDim.x) buf[i] = src[i];
    __syncthreads();
    if (b < N_B*C_) {
        int n = b >> 6, c = b & 63;
        for (int i = threadIdx.x; i < T_*V_; i += blockDim.x) {
            int v = i >> 6, t = i & 63;                 // i = v*64 + t
            g_xT[((size_t)(n*V_ + v))*PLANE + c*T_ + t] = buf[t*V_ + v];
        }
    } else {
        int c = b - N_B*C_;
        for (int i = threadIdx.x; i < T_*V_; i += blockDim.x) {
            int v = i >> 6, t = i & 63;
            g_peT[(size_t)v*PLANE + c*T_ + t] = buf[t*V_ + v];
        }
    }
}

// ---------------- K1: fused attention branch, one block per (n,v) ----------------
// dyn smem floats: xf 4096 | yf 4096 | w 4096 | fq/fk/fv/pq/pk 5*1024 | ao 1024 | mu 16 | aw 256 | ab 16
#define ATTN_SMEM_BYTES ((size_t)18720*4)
__global__ void k_attn(const float* __restrict__ dbg, const float* __restrict__ dbb,
                       const float* __restrict__ qkvw, const float* __restrict__ qkvb,
                       const float* __restrict__ aw,  const float* __restrict__ ab) {
    extern __shared__ float sm[];
    float* s_xf = sm;
    float* s_yf = sm + 4096;
    float* s_w  = sm + 8192;
    float* s_fq = sm + 12288;
    float* s_fk = sm + 13312;
    float* s_fv = sm + 14336;
    float* s_pq = sm + 15360;
    float* s_pk = sm + 16384;
    float* s_ao = sm + 17408;
    float* s_mu = sm + 18432;
    float* s_aw = sm + 18448;
    float* s_ab = sm + 18704;

    int tid = threadIdx.x;
    int n = blockIdx.x / V_, v = blockIdx.x % V_;
    const float* xp = g_xT  + (size_t)(n*V_ + v)*PLANE;
    const float* pp = g_peT + (size_t)v*PLANE;
    float rs = rsqrtf(1.f + EPS_);

    // phase 0: load plane, apply data_bn (xf) and +pe (yf); stage weights
    for (int idx = tid; idx < PLANE; idx += 256) {
        int c = idx >> 6;
        float xv = xp[idx];
        s_xf[idx] = xv * (__ldg(&dbg[c*V_ + v]) * rs) + __ldg(&dbb[c*V_ + v]);
        s_yf[idx] = xv + pp[idx];
    }
    for (int idx = tid; idx < 4096; idx += 256) s_w[idx] = qkvw[idx];
    if (tid < 256) s_aw[tid] = aw[tid];
    if (tid < 16)  s_ab[tid] = ab[tid];
    __syncthreads();

    // phase 1: QKV GEMMs. 80 row-jobs: 48 from xf (q,k,v rows), 32 from yf (pq,pk)
    {
        int tg = tid & 15, rg = tid >> 4;
        int t0 = tg * 4;
        for (int j = rg; j < 80; j += 16) {
            const float* src; int r;
            if (j < 48) { src = s_xf; r = (j < 32) ? j : j + 16; }  // skip g rows 32..47
            else        { src = s_yf; r = j - 48; }
            float bsv = __ldg(&qkvb[r]);
            float a0 = bsv, a1 = bsv, a2 = bsv, a3 = bsv;
            const float* wr = s_w + r*64;
            #pragma unroll
            for (int c = 0; c < 64; c++) {
                float4 xv = *(const float4*)&src[c*64 + t0];
                float  wv = wr[c];
                a0 += wv*xv.x; a1 += wv*xv.y; a2 += wv*xv.z; a3 += wv*xv.w;
            }
            float* dst; float scl = 1.f;
            if      (j < 16) { dst = s_fq + j*64;      scl = 0.70710678118f; }
            else if (j < 32) { dst = s_fk + (j-16)*64; }
            else if (j < 48) { dst = s_fv + (j-32)*64; }
            else if (j < 64) { dst = s_pq + (j-48)*64; scl = 0.70710678118f; }
            else             { dst = s_pk + (j-64)*64; }
            dst[t0+0] = a0*scl; dst[t0+1] = a1*scl; dst[t0+2] = a2*scl; dst[t0+3] = a3*scl;
        }
    }
    __syncthreads();

    // phase 2: mu_q = mean_t fq
    if (tid < 16) {
        float s = 0.f;
        #pragma unroll 8
        for (int t = 0; t < 64; t++) s += s_fq[tid*64 + t];
        s_mu[tid] = s * (1.f/64.f);
    }
    __syncthreads();

    // phase 3: attention core. thread = (s, head-group); 2 heads each.
    {
        int s = tid & 63, hg = tid >> 6;
        #pragma unroll
        for (int hh = 0; hh < 2; hh++) {
            int h = hg + 4*hh;
            int r0 = 2*h, r1 = 2*h + 1;
            float mu0 = s_mu[r0], mu1 = s_mu[r1];
            float fqc0 = s_fq[r0*64 + s] - mu0, fqc1 = s_fq[r1*64 + s] - mu1;
            float pq0 = s_pq[r0*64 + s], pq1 = s_pq[r1*64 + s];
            float a0 = 0.f, a1 = 0.f;
            #pragma unroll 4
            for (int t = 0; t < 64; t++) {
                float fk0 = s_fk[r0*64 + t], fk1 = s_fk[r1*64 + t];
                float pk0 = s_pk[r0*64 + t], pk1 = s_pk[r1*64 + t];
                float lp = pq0*pk0 + pq1*pk1;
                float pw = lp + fqc0*fk0 + fqc1*fk1;
                float un = lp + mu0*fk0 + mu1*fk1;
                float w = ftanh(pw) + ftanh(un);
                a0 += w * s_fv[r0*64 + t];
                a1 += w * s_fv[r1*64 + t];
            }
            s_ao[r0*64 + s] = a0;
            s_ao[r1*64 + s] = a1;
        }
    }
    __syncthreads();

    // phase 4: attn output projection (16x16) + residual, write channels 48..63
    {
        int t = tid & 63, og = tid >> 6;
        const float* xres = g_xT + (size_t)(n*V_ + v)*PLANE + 48*64;
        float*       outp = g_sR + (size_t)(n*V_ + v)*PLANE + 48*64;
        #pragma unroll
        for (int i = 0; i < 4; i++) {
            int o = og*4 + i;
            float acc = s_ab[o];
            #pragma unroll
            for (int c = 0; c < 16; c++) acc += s_aw[o*16 + c] * s_ao[c*64 + t];
            outp[o*64 + t] = acc + xres[o*64 + t];
        }
    }
}

// ---------------- K2: TCN branch (k=9 temporal conv, 48 out ch) ----------------
// 192 threads = 24 o-pairs x 8 t-groups(8). FFMA2-packed over the o-pair.
// dyn smem: w-pairs float2[24*580] (padded) + x halo float[64*72]
#define TCN_SMEM_BYTES ((size_t)(24*580*8 + 64*72*4))
__global__ void k_tcn(const float* __restrict__ tw, const float* __restrict__ tb,
                      const float* __restrict__ tbg, const float* __restrict__ tbb) {
    extern __shared__ float smr[];
    float2* s_w2 = (float2*)smr;           // 24*580 float2
    float*  s_xs = smr + 24*580*2;         // 64*72 floats
    int tid = threadIdx.x;
    int n = blockIdx.x / V_, v = blockIdx.x % V_;
    const float* xbase = g_xT + (size_t)(n*V_ + v)*PLANE;

    // stage weight pairs: s_w2[op*580 + c*9+k] = (w[2op][c][k], w[2op+1][c][k])
    for (int idx = tid; idx < 24*576; idx += 192) {
        int op = idx / 576, j = idx - op*576;       // j = c*9 + k
        float a = tw[(2*op  )*576 + j];
        float b = tw[(2*op+1)*576 + j];
        s_w2[op*580 + j] = make_float2(a, b);
    }
    // stage x rows with 4-wide zero halo on both sides
    for (int idx = tid; idx < 64*72; idx += 192) {
        int c = idx / 72, j = idx - c*72;
        int t = j - 4;
        s_xs[idx] = (t >= 0 && t < T_) ? xbase[c*T_ + t] : 0.f;
    }
    __syncthreads();

    int op = tid >> 3, tg = tid & 7;
    int t0 = tg * 8;
    unsigned long long acc2[8];
    #pragma unroll
    for (int i = 0; i < 8; i++) acc2[i] = 0ULL;

    for (int c = 0; c < 64; c++) {
        const float* xr = s_xs + c*72 + t0;
        float4 q0 = *(const float4*)(xr);
        float4 q1 = *(const float4*)(xr + 4);
        float4 q2 = *(const float4*)(xr + 8);
        float4 q3 = *(const float4*)(xr + 12);
        unsigned long long xd[16];
        xd[0]=dup2(q0.x); xd[1]=dup2(q0.y); xd[2]=dup2(q0.z); xd[3]=dup2(q0.w);
        xd[4]=dup2(q1.x); xd[5]=dup2(q1.y); xd[6]=dup2(q1.z); xd[7]=dup2(q1.w);
        xd[8]=dup2(q2.x); xd[9]=dup2(q2.y); xd[10]=dup2(q2.z); xd[11]=dup2(q2.w);
        xd[12]=dup2(q3.x); xd[13]=dup2(q3.y); xd[14]=dup2(q3.z); xd[15]=dup2(q3.w);
        const float2* wp = s_w2 + op*580 + c*9;
        #pragma unroll
        for (int k = 0; k < 9; k++) {
            unsigned long long w2 = *(const unsigned long long*)(wp + k);
            #pragma unroll
            for (int i = 0; i < 8; i++) acc2[i] = ffma2(w2, xd[i + k], acc2[i]);
        }
    }

    int o0 = 2*op, o1 = o0 + 1;
    float rsq = rsqrtf(1.f + EPS_);
    float ts0 = __ldg(&tbg[o0]) * rsq, ts1 = __ldg(&tbg[o1]) * rsq;
    float cb0 = __ldg(&tb[o0]) * ts0 + __ldg(&tbb[o0]);
    float cb1 = __ldg(&tb[o1]) * ts1 + __ldg(&tbb[o1]);
    float* out0 = g_sR + (size_t)(n*V_ + v)*PLANE + o0*T_;
    float* out1 = out0 + T_;
    #pragma unroll
    for (int i = 0; i < 8; i++) {
        float2 p = *(float2*)&acc2[i];
        int t = t0 + i;
        out0[t] = p.x*ts0 + cb0 + s_xs[o0*72 + 4 + t];   // + raw-x residual
        out1[t] = p.y*ts1 + cb1 + s_xs[o1*72 + 4 + t];
    }
}

// ---------------- K3: SE reduction + gate MLP, one block per n ----------------
__global__ void k_se(const float* __restrict__ f1w, const float* __restrict__ f1b,
                     const float* __restrict__ f2w, const float* __restrict__ f2b,
                     const float* __restrict__ bng) {
    __shared__ float s_red[64*65];
    __shared__ float s_se[64];
    __shared__ float s_h1[32];
    int n = blockIdx.x, tid = threadIdx.x;
    int t = tid & 63, cg = tid >> 6;
    float acc[16];
    #pragma unroll
    for (int j = 0; j < 16; j++) acc[j] = 0.f;
    const float* base = g_sR + (size_t)n*V_*PLANE;
    for (int v = 0; v < V_; v++) {
        const float* p = base + (size_t)v*PLANE;
        #pragma unroll
        for (int j = 0; j < 16; j++) acc[j] += p[(cg*16 + j)*64 + t];
    }
    #pragma unroll
    for (int j = 0; j < 16; j++) s_red[(cg*16 + j)*65 + t] = acc[j];
    __syncthreads();
    if (tid < 64) {
        float s2 = 0.f;
        #pragma unroll 8
        for (int tt = 0; tt < 64; tt++) s2 += s_red[tid*65 + tt];
        s_se[tid] = s2 * (1.f/1600.f);
    }
    __syncthreads();
    if (tid < 32) {
        float a = f1b[tid];
        #pragma unroll
        for (int c = 0; c < 64; c++) a += f1w[tid*64 + c] * s_se[c];
        s_h1[tid] = fmaxf(a, 0.f);
    }
    __syncthreads();
    if (tid < 64) {
        float a = f2b[tid];
        #pragma unroll
        for (int j = 0; j < 32; j++) a += f2w[tid*32 + j] * s_h1[j];
        float sg = __fdividef(1.f, 1.f + __expf(-a));
        g_gmul[n*64 + tid] = (1.f + sg) * bng[tid] * rsqrtf(1.f + EPS_);
    }
}

// ---------------- K4: gate * BN * ReLU + transpose back to (N,C,T,V) ----------------
__global__ void k_final(const float* __restrict__ bnb, float* __restrict__ out) {
    __shared__ float s_buf[25*65];
    int b = blockIdx.x;
    int n = b >> 6, c = b & 63;
    const float* base = g_sR + (size_t)n*V_*PLANE + c*T_;
    for (int idx = threadIdx.x; idx < T_*V_; idx += 256) {
        int v = idx >> 6, t = idx & 63;
        s_buf[v*65 + t] = base[(size_t)v*PLANE + t];
    }
    __syncthreads();
    float m = g_gmul[n*64 + c], bb = bnb[c];
    float* op = out + (size_t)(n*64 + c)*(T_*V_);
    for (int idx = threadIdx.x; idx < T_*V_; idx += 256) {
        int t = idx / 25, v = idx - t*25;           // out index = t*25 + v = idx
        float val = s_buf[v*65 + t] * m + bb;
        op[idx] = fmaxf(val, 0.f);
    }
}

// ---------------- launcher ----------------
extern "C" void kernel_launch(void* const* d_in, const int* in_sizes, int n_in,
                              void* d_out, int out_size) {
    (void)in_sizes; (void)n_in; (void)out_size;
    const float* x    = (const float*)d_in[0];
    const float* pe   = (const float*)d_in[1];
    const float* dbg  = (const float*)d_in[2];
    const float* dbb  = (const float*)d_in[3];
    const float* qkvw = (const float*)d_in[4];
    const float* qkvb = (const float*)d_in[5];
    const float* aw   = (const float*)d_in[6];
    const float* ab   = (const float*)d_in[7];
    const float* tw   = (const float*)d_in[8];
    const float* tb   = (const float*)d_in[9];
    const float* tbg  = (const float*)d_in[10];
    const float* tbb  = (const float*)d_in[11];
    const float* f1w  = (const float*)d_in[12];
    const float* f1b  = (const float*)d_in[13];
    const float* f2w  = (const float*)d_in[14];
    const float* f2b  = (const float*)d_in[15];
    const float* bng  = (const float*)d_in[16];
    const float* bnb  = (const float*)d_in[17];

    cudaFuncSetAttribute(k_attn, cudaFuncAttributeMaxDynamicSharedMemorySize, (int)ATTN_SMEM_BYTES);
    cudaFuncSetAttribute(k_tcn,  cudaFuncAttributeMaxDynamicSharedMemorySize, (int)TCN_SMEM_BYTES);

    k_transpose<<<N_B*C_ + C_, 256>>>(x, pe);
    k_attn<<<NV, 256, ATTN_SMEM_BYTES>>>(dbg, dbb, qkvw, qkvb, aw, ab);
    k_tcn <<<NV, 192, TCN_SMEM_BYTES>>>(tw, tb, tbg, tbb);
    k_se  <<<N_B, 256>>>(f1w, f1b, f2w, f2b, bng);
    k_final<<<N_B*C_, 256>>>(bnb, (float*)d_out);
}

// round 2
// speedup vs baseline: 1.0040x; 1.0040x over previous
#include <cuda_runtime.h>
#include <math.h>

// ---------------- problem constants ----------------
#define N_B   64
#define C_    64
#define T_    64
#define V_    25
#define NV    (N_B*V_)       // 1600 sequences
#define PLANE (C_*T_)        // 4096 floats per (n,v) plane
#define CTCN  48
#define EPS_  1e-5f

// ---------------- device scratch (no allocations allowed) ----------------
__device__ float g_xT [(size_t)NV*PLANE];   // x transposed: [n][v][c][t]
__device__ float g_peT[(size_t)V_*PLANE];   // pe transposed: [v][c][t]
__device__ float g_sR [(size_t)NV*PLANE];   // result (branches + residual): [n][v][c][t]
__device__ float g_gmul[N_B*C_];            // per-(n,ch) (1+gate)*bn_scale

// ---------------- helpers ----------------
__device__ __forceinline__ unsigned long long ffma2(unsigned long long a,
                                                    unsigned long long b,
                                                    unsigned long long c) {
    unsigned long long d;
    asm("fma.rn.f32x2 %0, %1, %2, %3;" : "=l"(d) : "l"(a), "l"(b), "l"(c));
    return d;
}
__device__ __forceinline__ unsigned long long dup2(float a) {
    unsigned long long r;
    asm("mov.b64 %0, {%1, %1};" : "=l"(r) : "f"(a));
    return r;
}
__device__ __forceinline__ float ftanh(float x) {
    x = fminf(15.f, fmaxf(-15.f, x));
    float e = __expf(2.f * x);
    return __fdividef(e - 1.f, e + 1.f);
}

// ---------------- K0: transpose x and pe into [.. ][c][t] planes ----------------
__global__ void k_transpose(const float* __restrict__ x, const float* __restrict__ pe) {
    __shared__ float buf[T_*V_];
    int b = blockIdx.x;
    const float* src = (b < N_B*C_) ? (x + (size_t)b*(T_*V_))
                                    : (pe + (size_t)(b - N_B*C_)*(T_*V_));
    for (int i = threadIdx.x; i < T_*V_; i += blockDim.x) buf[i] = src[i];
    __syncthreads();
    if (b < N_B*C_) {
        int n = b >> 6, c = b & 63;
        for (int i = threadIdx.x; i < T_*V_; i += blockDim.x) {
            int v = i >> 6, t = i & 63;                 // i = v*64 + t
            g_xT[((size_t)(n*V_ + v))*PLANE + c*T_ + t] = buf[t*V_ + v];
        }
    } else {
        int c = b - N_B*C_;
        for (int i = threadIdx.x; i < T_*V_; i += blockDim.x) {
            int v = i >> 6, t = i & 63;
            g_peT[(size_t)v*PLANE + c*T_ + t] = buf[t*V_ + v];
        }
    }
}

// ---------------- K1: fused attention branch, one block per (n,v) ----------------
// dyn smem floats: xf 4096 | yf 4096 | w 4096 | fq/fk/fv/pq/pk 5*1024 | ao 1024 | mu 16 | aw 256 | ab 16
#define ATTN_SMEM_BYTES ((size_t)18720*4)
__global__ void k_attn(const float* __restrict__ dbg, const float* __restrict__ dbb,
                       const float* __restrict__ qkvw, const float* __restrict__ qkvb,
                       const float* __restrict__ aw,  const float* __restrict__ ab) {
    extern __shared__ float sm[];
    float* s_xf = sm;
    float* s_yf = sm + 4096;
    float* s_w  = sm + 8192;
    float* s_fq = sm + 12288;
    float* s_fk = sm + 13312;
    float* s_fv = sm + 14336;
    float* s_pq = sm + 15360;
    float* s_pk = sm + 16384;
    float* s_ao = sm + 17408;
    float* s_mu = sm + 18432;
    float* s_aw = sm + 18448;
    float* s_ab = sm + 18704;

    int tid = threadIdx.x;
    int n = blockIdx.x / V_, v = blockIdx.x % V_;
    const float* xp = g_xT  + (size_t)(n*V_ + v)*PLANE;
    const float* pp = g_peT + (size_t)v*PLANE;
    float rs = rsqrtf(1.f + EPS_);

    // phase 0: load plane, apply data_bn (xf) and +pe (yf); stage weights
    for (int idx = tid; idx < PLANE; idx += 256) {
        int c = idx >> 6;
        float xv = xp[idx];
        s_xf[idx] = xv * (__ldg(&dbg[c*V_ + v]) * rs) + __ldg(&dbb[c*V_ + v]);
        s_yf[idx] = xv + pp[idx];
    }
    for (int idx = tid; idx < 4096; idx += 256) s_w[idx] = qkvw[idx];
    if (tid < 256) s_aw[tid] = aw[tid];
    if (tid < 16)  s_ab[tid] = ab[tid];
    __syncthreads();

    // phase 1: QKV GEMMs. 80 row-jobs: 48 from xf (q,k,v rows), 32 from yf (pq,pk)
    {
        int tg = tid & 15, rg = tid >> 4;
        int t0 = tg * 4;
        for (int j = rg; j < 80; j += 16) {
            const float* src; int r;
            if (j < 48) { src = s_xf; r = (j < 32) ? j : j + 16; }  // skip g rows 32..47
            else        { src = s_yf; r = j - 48; }
            float bsv = __ldg(&qkvb[r]);
            float a0 = bsv, a1 = bsv, a2 = bsv, a3 = bsv;
            const float* wr = s_w + r*64;
            #pragma unroll
            for (int c = 0; c < 64; c++) {
                float4 xv = *(const float4*)&src[c*64 + t0];
                float  wv = wr[c];
                a0 += wv*xv.x; a1 += wv*xv.y; a2 += wv*xv.z; a3 += wv*xv.w;
            }
            float* dst; float scl = 1.f;
            if      (j < 16) { dst = s_fq + j*64;      scl = 0.70710678118f; }
            else if (j < 32) { dst = s_fk + (j-16)*64; }
            else if (j < 48) { dst = s_fv + (j-32)*64; }
            else if (j < 64) { dst = s_pq + (j-48)*64; scl = 0.70710678118f; }
            else             { dst = s_pk + (j-64)*64; }
            dst[t0+0] = a0*scl; dst[t0+1] = a1*scl; dst[t0+2] = a2*scl; dst[t0+3] = a3*scl;
        }
    }
    __syncthreads();

    // phase 2: mu_q = mean_t fq
    if (tid < 16) {
        float s = 0.f;
        #pragma unroll 8
        for (int t = 0; t < 64; t++) s += s_fq[tid*64 + t];
        s_mu[tid] = s * (1.f/64.f);
    }
    __syncthreads();

    // phase 3: attention core. thread = (s, head-group); 2 heads each.
    {
        int s = tid & 63, hg = tid >> 6;
        #pragma unroll
        for (int hh = 0; hh < 2; hh++) {
            int h = hg + 4*hh;
            int r0 = 2*h, r1 = 2*h + 1;
            float mu0 = s_mu[r0], mu1 = s_mu[r1];
            float fqc0 = s_fq[r0*64 + s] - mu0, fqc1 = s_fq[r1*64 + s] - mu1;
            float pq0 = s_pq[r0*64 + s], pq1 = s_pq[r1*64 + s];
            float a0 = 0.f, a1 = 0.f;
            #pragma unroll 4
            for (int t = 0; t < 64; t++) {
                float fk0 = s_fk[r0*64 + t], fk1 = s_fk[r1*64 + t];
                float pk0 = s_pk[r0*64 + t], pk1 = s_pk[r1*64 + t];
                float lp = pq0*pk0 + pq1*pk1;
                float pw = lp + fqc0*fk0 + fqc1*fk1;
                float un = lp + mu0*fk0 + mu1*fk1;
                float w = ftanh(pw) + ftanh(un);
                a0 += w * s_fv[r0*64 + t];
                a1 += w * s_fv[r1*64 + t];
            }
            s_ao[r0*64 + s] = a0;
            s_ao[r1*64 + s] = a1;
        }
    }
    __syncthreads();

    // phase 4: attn output projection (16x16) + residual, write channels 48..63
    {
        int t = tid & 63, og = tid >> 6;
        const float* xres = g_xT + (size_t)(n*V_ + v)*PLANE + 48*64;
        float*       outp = g_sR + (size_t)(n*V_ + v)*PLANE + 48*64;
        #pragma unroll
        for (int i = 0; i < 4; i++) {
            int o = og*4 + i;
            float acc = s_ab[o];
            #pragma unroll
            for (int c = 0; c < 16; c++) acc += s_aw[o*16 + c] * s_ao[c*64 + t];
            outp[o*64 + t] = acc + xres[o*64 + t];
        }
    }
}

// ---------------- K2: TCN branch (k=9 temporal conv, 48 out ch) ----------------
// 192 threads = 24 o-pairs x 8 t-groups(8). FFMA2-packed over the o-pair.
// dyn smem: w-pairs float2[24*580] (padded) + x halo float[64*72]
#define TCN_SMEM_BYTES ((size_t)(24*580*8 + 64*72*4))
__global__ void k_tcn(const float* __restrict__ tw, const float* __restrict__ tb,
                      const float* __restrict__ tbg, const float* __restrict__ tbb) {
    extern __shared__ float smr[];
    float2* s_w2 = (float2*)smr;           // 24*580 float2
    float*  s_xs = smr + 24*580*2;         // 64*72 floats
    int tid = threadIdx.x;
    int n = blockIdx.x / V_, v = blockIdx.x % V_;
    const float* xbase = g_xT + (size_t)(n*V_ + v)*PLANE;

    // stage weight pairs: s_w2[op*580 + c*9+k] = (w[2op][c][k], w[2op+1][c][k])
    for (int idx = tid; idx < 24*576; idx += 192) {
        int op = idx / 576, j = idx - op*576;       // j = c*9 + k
        float a = tw[(2*op  )*576 + j];
        float b = tw[(2*op+1)*576 + j];
        s_w2[op*580 + j] = make_float2(a, b);
    }
    // stage x rows with 4-wide zero halo on both sides
    for (int idx = tid; idx < 64*72; idx += 192) {
        int c = idx / 72, j = idx - c*72;
        int t = j - 4;
        s_xs[idx] = (t >= 0 && t < T_) ? xbase[c*T_ + t] : 0.f;
    }
    __syncthreads();

    int op = tid >> 3, tg = tid & 7;
    int t0 = tg * 8;
    unsigned long long acc2[8];
    #pragma unroll
    for (int i = 0; i < 8; i++) acc2[i] = 0ULL;

    for (int c = 0; c < 64; c++) {
        const float* xr = s_xs + c*72 + t0;
        float4 q0 = *(const float4*)(xr);
        float4 q1 = *(const float4*)(xr + 4);
        float4 q2 = *(const float4*)(xr + 8);
        float4 q3 = *(const float4*)(xr + 12);
        unsigned long long xd[16];
        xd[0]=dup2(q0.x); xd[1]=dup2(q0.y); xd[2]=dup2(q0.z); xd[3]=dup2(q0.w);
        xd[4]=dup2(q1.x); xd[5]=dup2(q1.y); xd[6]=dup2(q1.z); xd[7]=dup2(q1.w);
        xd[8]=dup2(q2.x); xd[9]=dup2(q2.y); xd[10]=dup2(q2.z); xd[11]=dup2(q2.w);
        xd[12]=dup2(q3.x); xd[13]=dup2(q3.y); xd[14]=dup2(q3.z); xd[15]=dup2(q3.w);
        const float2* wp = s_w2 + op*580 + c*9;
        #pragma unroll
        for (int k = 0; k < 9; k++) {
            unsigned long long w2 = *(const unsigned long long*)(wp + k);
            #pragma unroll
            for (int i = 0; i < 8; i++) acc2[i] = ffma2(w2, xd[i + k], acc2[i]);
        }
    }

    int o0 = 2*op, o1 = o0 + 1;
    float rsq = rsqrtf(1.f + EPS_);
    float ts0 = __ldg(&tbg[o0]) * rsq, ts1 = __ldg(&tbg[o1]) * rsq;
    float cb0 = __ldg(&tb[o0]) * ts0 + __ldg(&tbb[o0]);
    float cb1 = __ldg(&tb[o1]) * ts1 + __ldg(&tbb[o1]);
    float* out0 = g_sR + (size_t)(n*V_ + v)*PLANE + o0*T_;
    float* out1 = out0 + T_;
    #pragma unroll
    for (int i = 0; i < 8; i++) {
        float2 p = *(float2*)&acc2[i];
        int t = t0 + i;
        out0[t] = p.x*ts0 + cb0 + s_xs[o0*72 + 4 + t];   // + raw-x residual
        out1[t] = p.y*ts1 + cb1 + s_xs[o1*72 + 4 + t];
    }
}

// ---------------- K3: SE reduction + gate MLP, one block per n ----------------
__global__ void k_se(const float* __restrict__ f1w, const float* __restrict__ f1b,
                     const float* __restrict__ f2w, const float* __restrict__ f2b,
                     const float* __restrict__ bng) {
    __shared__ float s_red[64*65];
    __shared__ float s_se[64];
    __shared__ float s_h1[32];
    int n = blockIdx.x, tid = threadIdx.x;
    int t = tid & 63, cg = tid >> 6;
    float acc[16];
    #pragma unroll
    for (int j = 0; j < 16; j++) acc[j] = 0.f;
    const float* base = g_sR + (size_t)n*V_*PLANE;
    for (int v = 0; v < V_; v++) {
        const float* p = base + (size_t)v*PLANE;
        #pragma unroll
        for (int j = 0; j < 16; j++) acc[j] += p[(cg*16 + j)*64 + t];
    }
    #pragma unroll
    for (int j = 0; j < 16; j++) s_red[(cg*16 + j)*65 + t] = acc[j];
    __syncthreads();
    if (tid < 64) {
        float s2 = 0.f;
        #pragma unroll 8
        for (int tt = 0; tt < 64; tt++) s2 += s_red[tid*65 + tt];
        s_se[tid] = s2 * (1.f/1600.f);
    }
    __syncthreads();
    if (tid < 32) {
        float a = f1b[tid];
        #pragma unroll
        for (int c = 0; c < 64; c++) a += f1w[tid*64 + c] * s_se[c];
        s_h1[tid] = fmaxf(a, 0.f);
    }
    __syncthreads();
    if (tid < 64) {
        float a = f2b[tid];
        #pragma unroll
        for (int j = 0; j < 32; j++) a += f2w[tid*32 + j] * s_h1[j];
        float sg = __fdividef(1.f, 1.f + __expf(-a));
        g_gmul[n*64 + tid] = (1.f + sg) * bng[tid] * rsqrtf(1.f + EPS_);
    }
}

// ---------------- K4: gate * BN * ReLU + transpose back to (N,C,T,V) ----------------
__global__ void k_final(const float* __restrict__ bnb, float* __restrict__ out) {
    __shared__ float s_buf[25*65];
    int b = blockIdx.x;
    int n = b >> 6, c = b & 63;
    const float* base = g_sR + (size_t)n*V_*PLANE + c*T_;
    for (int idx = threadIdx.x; idx < T_*V_; idx += 256) {
        int v = idx >> 6, t = idx & 63;
        s_buf[v*65 + t] = base[(size_t)v*PLANE + t];
    }
    __syncthreads();
    float m = g_gmul[n*64 + c], bb = bnb[c];
    float* op = out + (size_t)(n*64 + c)*(T_*V_);
    for (int idx = threadIdx.x; idx < T_*V_; idx += 256) {
        int t = idx / 25, v = idx - t*25;           // out index = t*25 + v = idx
        float val = s_buf[v*65 + t] * m + bb;
        op[idx] = fmaxf(val, 0.f);
    }
}

// ---------------- launcher ----------------
extern "C" void kernel_launch(void* const* d_in, const int* in_sizes, int n_in,
                              void* d_out, int out_size) {
    (void)in_sizes; (void)n_in; (void)out_size;
    const float* x    = (const float*)d_in[0];
    const float* pe   = (const float*)d_in[1];
    const float* dbg  = (const float*)d_in[2];
    const float* dbb  = (const float*)d_in[3];
    const float* qkvw = (const float*)d_in[4];
    const float* qkvb = (const float*)d_in[5];
    const float* aw   = (const float*)d_in[6];
    const float* ab   = (const float*)d_in[7];
    const float* tw   = (const float*)d_in[8];
    const float* tb   = (const float*)d_in[9];
    const float* tbg  = (const float*)d_in[10];
    const float* tbb  = (const float*)d_in[11];
    const float* f1w  = (const float*)d_in[12];
    const float* f1b  = (const float*)d_in[13];
    const float* f2w  = (const float*)d_in[14];
    const float* f2b  = (const float*)d_in[15];
    const float* bng  = (const float*)d_in[16];
    const float* bnb  = (const float*)d_in[17];

    cudaFuncSetAttribute(k_attn, cudaFuncAttributeMaxDynamicSharedMemorySize, (int)ATTN_SMEM_BYTES);
    cudaFuncSetAttribute(k_tcn,  cudaFuncAttributeMaxDynamicSharedMemorySize, (int)TCN_SMEM_BYTES);

    k_transpose<<<N_B*C_ + C_, 256>>>(x, pe);
    k_attn<<<NV, 256, ATTN_SMEM_BYTES>>>(dbg, dbb, qkvw, qkvb, aw, ab);
    k_tcn <<<NV, 192, TCN_SMEM_BYTES>>>(tw, tb, tbg, tbb);
    k_se  <<<N_B, 256>>>(f1w, f1b, f2w, f2b, bng);
    k_final<<<N_B*C_, 256>>>(bnb, (float*)d_out);
}

// round 6
// speedup vs baseline: 1.2810x; 1.2758x over previous
#include <cuda_runtime.h>
#include <math.h>

// ---------------- problem constants ----------------
#define N_B   64
#define C_    64
#define T_    64
#define V_    25
#define NV    (N_B*V_)       // 1600 sequences
#define PLANE (C_*T_)        // 4096 floats per (n,v) plane
#define EPS_  1e-5f

typedef unsigned long long u64;

// ---------------- device scratch (no allocations allowed) ----------------
__device__ float g_xT [(size_t)NV*PLANE];   // x transposed: [n][v][c][t]
__device__ float g_peT[(size_t)V_*PLANE];   // pe transposed: [v][c][t]
__device__ float g_sR [(size_t)NV*PLANE];   // result (branches + residual): [n][v][c][t]
__device__ float g_part[(size_t)NV*C_];     // per-(n,v,c) sums over t (for SE)
__device__ float g_gmul[N_B*C_];            // per-(n,ch) (1+gate)*bn_scale

// ---------------- helpers ----------------
__device__ __forceinline__ u64 ffma2(u64 a, u64 b, u64 c) {
    u64 d;
    asm("fma.rn.f32x2 %0, %1, %2, %3;" : "=l"(d) : "l"(a), "l"(b), "l"(c));
    return d;
}
__device__ __forceinline__ u64 dup2(float a) {
    u64 r;
    asm("mov.b64 %0, {%1, %1};" : "=l"(r) : "f"(a));
    return r;
}
__device__ __forceinline__ u64 pack2(float lo, float hi) {
    u64 r;
    asm("mov.b64 %0, {%1, %2};" : "=l"(r) : "f"(lo), "f"(hi));
    return r;
}
__device__ __forceinline__ float tanha(float x) {
    float y;
    asm("tanh.approx.f32 %0, %1;" : "=f"(y) : "f"(x));
    return y;
}

// ---------------- K0: transpose x and pe into [..][c][t] planes ----------------
__global__ void k_transpose(const float* __restrict__ x, const float* __restrict__ pe) {
    __shared__ float buf[T_*V_];
    int b = blockIdx.x;
    const float* src = (b < N_B*C_) ? (x + (size_t)b*(T_*V_))
                                    : (pe + (size_t)(b - N_B*C_)*(T_*V_));
    for (int i = threadIdx.x; i < T_*V_; i += blockDim.x) buf[i] = src[i];
    __syncthreads();
    if (b < N_B*C_) {
        int n = b >> 6, c = b & 63;
        for (int i = threadIdx.x; i < T_*V_; i += blockDim.x) {
            int v = i >> 6, t = i & 63;
            g_xT[((size_t)(n*V_ + v))*PLANE + c*T_ + t] = buf[t*V_ + v];
        }
    } else {
        int c = b - N_B*C_;
        for (int i = threadIdx.x; i < T_*V_; i += blockDim.x) {
            int v = i >> 6, t = i & 63;
            g_peT[(size_t)v*PLANE + c*T_ + t] = buf[t*V_ + v];
        }
    }
}

// ---------------- K1: fused attention branch, one block per (n,v) ----------------
// smem floats: xf 4096 | yf 4096 | w 4096 | fq/fk/fv/pq/pk 5*1024 | ao 1024 | mu 16 | aw 256 | ab 16 | scr 32
#define ATTN_SMEM_BYTES ((size_t)18752*4)
__global__ __launch_bounds__(256)
void k_attn(const float* __restrict__ dbg, const float* __restrict__ dbb,
            const float* __restrict__ qkvw, const float* __restrict__ qkvb,
            const float* __restrict__ aw,  const float* __restrict__ ab) {
    extern __shared__ float sm[];
    float* s_xf = sm;
    float* s_yf = sm + 4096;
    float* s_w  = sm + 8192;
    float* s_fq = sm + 12288;
    float* s_fk = sm + 13312;
    float* s_fv = sm + 14336;
    float* s_pq = sm + 15360;
    float* s_pk = sm + 16384;
    float* s_ao = sm + 17408;
    float* s_mu = sm + 18432;
    float* s_aw = sm + 18448;
    float* s_ab = sm + 18704;
    float* s_scr= sm + 18720;

    int tid = threadIdx.x;
    int n = blockIdx.x / V_, v = blockIdx.x % V_;
    const float* xp = g_xT  + (size_t)(n*V_ + v)*PLANE;
    const float* pp = g_peT + (size_t)v*PLANE;
    float rs = rsqrtf(1.f + EPS_);

    // phase 0: load plane, apply data_bn (xf) and +pe (yf); stage weights
    for (int idx = tid; idx < PLANE; idx += 256) {
        int c = idx >> 6;
        float xv = xp[idx];
        s_xf[idx] = xv * (__ldg(&dbg[c*V_ + v]) * rs) + __ldg(&dbb[c*V_ + v]);
        s_yf[idx] = xv + pp[idx];
    }
    for (int idx = tid; idx < 4096; idx += 256) s_w[idx] = qkvw[idx];
    if (tid < 256) s_aw[tid] = aw[tid];
    if (tid < 16)  s_ab[tid] = ab[tid];
    __syncthreads();

    // phase 1: QKV GEMMs (f32x2 packed). 80 row-jobs.
    {
        int tg = tid & 15, rg = tid >> 4;
        int t0 = tg * 4;
        for (int j = rg; j < 80; j += 16) {
            const float* src; int r;
            if (j < 48) { src = s_xf; r = (j < 32) ? j : j + 16; }  // skip g rows
            else        { src = s_yf; r = j - 48; }
            float bsv = __ldg(&qkvb[r]);
            u64 a0 = dup2(bsv), a1 = dup2(bsv);
            const float* wr = s_w + r*64;
            #pragma unroll
            for (int c = 0; c < 64; c++) {
                const u64* xq = (const u64*)&src[c*64 + t0];
                u64 x0 = xq[0];
                u64 x1 = xq[1];
                u64 wd = dup2(wr[c]);
                a0 = ffma2(wd, x0, a0);
                a1 = ffma2(wd, x1, a1);
            }
            float* dst; float scl = 1.f;
            if      (j < 16) { dst = s_fq + j*64;      scl = 0.70710678118f; }
            else if (j < 32) { dst = s_fk + (j-16)*64; }
            else if (j < 48) { dst = s_fv + (j-32)*64; }
            else if (j < 64) { dst = s_pq + (j-48)*64; scl = 0.70710678118f; }
            else             { dst = s_pk + (j-64)*64; }
            float2 A0 = *(float2*)&a0, A1 = *(float2*)&a1;
            dst[t0+0] = A0.x*scl; dst[t0+1] = A0.y*scl;
            dst[t0+2] = A1.x*scl; dst[t0+3] = A1.y*scl;
        }
    }
    __syncthreads();

    // phase 2: mu_q = mean_t fq
    if (tid < 16) {
        float s = 0.f;
        #pragma unroll 8
        for (int t = 0; t < 64; t++) s += s_fq[tid*64 + t];
        s_mu[tid] = s * (1.f/64.f);
    }
    __syncthreads();

    // phase 3: attention core, t-pair f32x2 packed, tanh.approx
    {
        int s = tid & 63, hg = tid >> 6;
        #pragma unroll
        for (int hh = 0; hh < 2; hh++) {
            int h = hg + 4*hh;
            int r0 = 2*h, r1 = 2*h + 1;
            float mu0 = s_mu[r0], mu1 = s_mu[r1];
            u64 mu0d = dup2(mu0), mu1d = dup2(mu1);
            u64 fq0d = dup2(s_fq[r0*64 + s] - mu0);
            u64 fq1d = dup2(s_fq[r1*64 + s] - mu1);
            u64 pq0d = dup2(s_pq[r0*64 + s]);
            u64 pq1d = dup2(s_pq[r1*64 + s]);
            const u64* fk0p = (const u64*)&s_fk[r0*64];
            const u64* fk1p = (const u64*)&s_fk[r1*64];
            const u64* pk0p = (const u64*)&s_pk[r0*64];
            const u64* pk1p = (const u64*)&s_pk[r1*64];
            const u64* fv0p = (const u64*)&s_fv[r0*64];
            const u64* fv1p = (const u64*)&s_fv[r1*64];
            u64 a0 = 0ULL, a1 = 0ULL;
            #pragma unroll 4
            for (int tp = 0; tp < 32; tp++) {
                u64 fk0 = fk0p[tp], fk1 = fk1p[tp];
                u64 pk0 = pk0p[tp], pk1 = pk1p[tp];
                u64 lp = ffma2(pq1d, pk1, ffma2(pq0d, pk0, 0ULL));
                u64 pw = ffma2(fq1d, fk1, ffma2(fq0d, fk0, lp));
                u64 un = ffma2(mu1d, fk1, ffma2(mu0d, fk0, lp));
                float2 pwf = *(float2*)&pw, unf = *(float2*)&un;
                float w0 = tanha(pwf.x) + tanha(unf.x);
                float w1 = tanha(pwf.y) + tanha(unf.y);
                u64 w2 = pack2(w0, w1);
                a0 = ffma2(w2, fv0p[tp], a0);
                a1 = ffma2(w2, fv1p[tp], a1);
            }
            float2 A0 = *(float2*)&a0, A1 = *(float2*)&a1;
            s_ao[r0*64 + s] = A0.x + A0.y;
            s_ao[r1*64 + s] = A1.x + A1.y;
        }
    }
    __syncthreads();

    // phase 4: attn output projection (16x16) + residual + SE partials (ch 48..63)
    {
        int t = tid & 63, og = tid >> 6;
        const float* xres = g_xT + (size_t)(n*V_ + v)*PLANE + 48*64;
        float*       outp = g_sR + (size_t)(n*V_ + v)*PLANE + 48*64;
        int half = t >> 5;
        #pragma unroll
        for (int i = 0; i < 4; i++) {
            int o = og*4 + i;
            float acc = s_ab[o];
            #pragma unroll
            for (int c = 0; c < 16; c++) acc += s_aw[o*16 + c] * s_ao[c*64 + t];
            float res = acc + xres[o*64 + t];
            outp[o*64 + t] = res;
            // deterministic warp reduction over 32 t's
            float vsum = res;
            #pragma unroll
            for (int off = 16; off > 0; off >>= 1)
                vsum += __shfl_down_sync(0xffffffffu, vsum, off);
            if ((t & 31) == 0) s_scr[o*2 + half] = vsum;
        }
    }
    __syncthreads();
    if (tid < 16)
        g_part[(size_t)(n*V_ + v)*64 + 48 + tid] = s_scr[2*tid] + s_scr[2*tid+1];
}

// ---------------- K2: TCN branch, 2 planes per block ----------------
// 384 threads = 2 planes x (24 o-pairs x 8 t-groups). FFMA2-packed over o-pair.
#define TCN_PL 2
#define TCN_THREADS (192*TCN_PL)
#define TCN_SMEM_BYTES ((size_t)(24*580*8 + TCN_PL*64*72*4))
__global__ __launch_bounds__(TCN_THREADS, 1)
void k_tcn(const float* __restrict__ tw, const float* __restrict__ tb,
           const float* __restrict__ tbg, const float* __restrict__ tbb) {
    extern __shared__ float smr[];
    float2* s_w2 = (float2*)smr;                 // 24*580 float2
    float*  s_xs = smr + 24*580*2;               // TCN_PL * 64*72 floats
    int tid = threadIdx.x;
    int plane0 = blockIdx.x * TCN_PL;

    // stage weight pairs
    for (int idx = tid; idx < 24*576; idx += TCN_THREADS) {
        int op = idx / 576, j = idx - op*576;
        float a = tw[(2*op  )*576 + j];
        float b = tw[(2*op+1)*576 + j];
        s_w2[op*580 + j] = make_float2(a, b);
    }
    // stage x rows (both planes) with 4-wide zero halo
    for (int idx = tid; idx < TCN_PL*64*72; idx += TCN_THREADS) {
        int pl = idx / 4608, rem = idx - pl*4608;
        int c = rem / 72, j = rem - c*72;
        int t = j - 4;
        s_xs[idx] = (t >= 0 && t < T_)
                  ? g_xT[(size_t)(plane0 + pl)*PLANE + c*T_ + t] : 0.f;
    }
    __syncthreads();

    int pl = tid / 192, r = tid - pl*192;
    int op = r >> 3, tg = r & 7;
    int t0 = tg * 8;
    const float* xs = s_xs + pl*4608;

    u64 acc2[8];
    #pragma unroll
    for (int i = 0; i < 8; i++) acc2[i] = 0ULL;

    for (int c = 0; c < 64; c++) {
        const float* xr = xs + c*72 + t0;
        u64 xd[16];
        #pragma unroll
        for (int i = 0; i < 16; i++) xd[i] = dup2(xr[i]);
        const float2* wp = s_w2 + op*580 + c*9;
        #pragma unroll
        for (int k = 0; k < 9; k++) {
            u64 w2 = *(const u64*)(wp + k);
            #pragma unroll
            for (int i = 0; i < 8; i++) acc2[i] = ffma2(w2, xd[i + k], acc2[i]);
        }
    }

    int o0 = 2*op, o1 = o0 + 1;
    float rsq = rsqrtf(1.f + EPS_);
    float ts0 = __ldg(&tbg[o0]) * rsq, ts1 = __ldg(&tbg[o1]) * rsq;
    float cb0 = __ldg(&tb[o0]) * ts0 + __ldg(&tbb[o0]);
    float cb1 = __ldg(&tb[o1]) * ts1 + __ldg(&tbb[o1]);
    float* out0 = g_sR + (size_t)(plane0 + pl)*PLANE + o0*T_;
    float* out1 = out0 + T_;
    float s0 = 0.f, s1 = 0.f;
    #pragma unroll
    for (int i = 0; i < 8; i++) {
        float2 p = *(float2*)&acc2[i];
        int t = t0 + i;
        float v0 = p.x*ts0 + cb0 + xs[o0*72 + 4 + t];   // + raw-x residual
        float v1 = p.y*ts1 + cb1 + xs[o1*72 + 4 + t];
        out0[t] = v0; out1[t] = v1;
        s0 += v0; s1 += v1;
    }
    // deterministic reduction over the 8-lane octet (same op)
    #pragma unroll
    for (int off = 4; off > 0; off >>= 1) {
        s0 += __shfl_down_sync(0xffffffffu, s0, off, 8);
        s1 += __shfl_down_sync(0xffffffffu, s1, off, 8);
    }
    if (tg == 0) {
        g_part[(size_t)(plane0 + pl)*64 + o0] = s0;
        g_part[(size_t)(plane0 + pl)*64 + o1] = s1;
    }
}

// ---------------- K3: SE gate MLP from partials, one block per n ----------------
__global__ void k_se(const float* __restrict__ f1w, const float* __restrict__ f1b,
                     const float* __restrict__ f2w, const float* __restrict__ f2b,
                     const float* __restrict__ bng) {
    __shared__ float s_se[64];
    __shared__ float s_h1[32];
    int n = blockIdx.x, c = threadIdx.x;
    float s = 0.f;
    for (int v = 0; v < V_; v++) s += g_part[(size_t)(n*V_ + v)*64 + c];
    s_se[c] = s * (1.f/1600.f);
    __syncthreads();
    if (c < 32) {
        float a = f1b[c];
        #pragma unroll
        for (int j = 0; j < 64; j++) a += f1w[c*64 + j] * s_se[j];
        s_h1[c] = fmaxf(a, 0.f);
    }
    __syncthreads();
    float a = f2b[c];
    #pragma unroll
    for (int j = 0; j < 32; j++) a += f2w[c*32 + j] * s_h1[j];
    float sg = __fdividef(1.f, 1.f + __expf(-a));
    g_gmul[n*64 + c] = (1.f + sg) * bng[c] * rsqrtf(1.f + EPS_);
}

// ---------------- K4: gate * BN * ReLU + transpose back to (N,C,T,V) ----------------
__global__ void k_final(const float* __restrict__ bnb, float* __restrict__ out) {
    __shared__ float s_buf[25*65];
    int b = blockIdx.x;
    int n = b >> 6, c = b & 63;
    const float* base = g_sR + (size_t)n*V_*PLANE + c*T_;
    for (int idx = threadIdx.x; idx < T_*V_; idx += 256) {
        int v = idx >> 6, t = idx & 63;
        s_buf[v*65 + t] = base[(size_t)v*PLANE + t];
    }
    __syncthreads();
    float m = g_gmul[n*64 + c], bb = bnb[c];
    float* op = out + (size_t)(n*64 + c)*(T_*V_);
    for (int idx = threadIdx.x; idx < T_*V_; idx += 256) {
        int t = idx / 25, v = idx - t*25;
        float val = s_buf[v*65 + t] * m + bb;
        op[idx] = fmaxf(val, 0.f);
    }
}

// ---------------- launcher ----------------
extern "C" void kernel_launch(void* const* d_in, const int* in_sizes, int n_in,
                              void* d_out, int out_size) {
    (void)in_sizes; (void)n_in; (void)out_size;
    const float* x    = (const float*)d_in[0];
    const float* pe   = (const float*)d_in[1];
    const float* dbg  = (const float*)d_in[2];
    const float* dbb  = (const float*)d_in[3];
    const float* qkvw = (const float*)d_in[4];
    const float* qkvb = (const float*)d_in[5];
    const float* aw   = (const float*)d_in[6];
    const float* ab   = (const float*)d_in[7];
    const float* tw   = (const float*)d_in[8];
    const float* tb   = (const float*)d_in[9];
    const float* tbg  = (const float*)d_in[10];
    const float* tbb  = (const float*)d_in[11];
    const float* f1w  = (const float*)d_in[12];
    const float* f1b  = (const float*)d_in[13];
    const float* f2w  = (const float*)d_in[14];
    const float* f2b  = (const float*)d_in[15];
    const float* bng  = (const float*)d_in[16];
    const float* bnb  = (const float*)d_in[17];

    cudaFuncSetAttribute(k_attn, cudaFuncAttributeMaxDynamicSharedMemorySize, (int)ATTN_SMEM_BYTES);
    cudaFuncSetAttribute(k_tcn,  cudaFuncAttributeMaxDynamicSharedMemorySize, (int)TCN_SMEM_BYTES);

    k_transpose<<<N_B*C_ + C_, 256>>>(x, pe);
    k_attn<<<NV, 256, ATTN_SMEM_BYTES>>>(dbg, dbb, qkvw, qkvb, aw, ab);
    k_tcn <<<NV/TCN_PL, TCN_THREADS, TCN_SMEM_BYTES>>>(tw, tb, tbg, tbb);
    k_se  <<<N_B, 64>>>(f1w, f1b, f2w, f2b, bng);
    k_final<<<N_B*C_, 256>>>(bnb, (float*)d_out);
}

// round 8
// speedup vs baseline: 1.3936x; 1.0879x over previous
#include <cuda_runtime.h>
#include <math.h>

// ---------------- problem constants ----------------
#define N_B   64
#define C_    64
#define T_    64
#define V_    25
#define NV    (N_B*V_)       // 1600 sequences
#define PLANE (C_*T_)        // 4096 floats per (n,v) plane
#define EPS_  1e-5f

typedef unsigned long long u64;

// ---------------- device scratch (no allocations allowed) ----------------
__device__ float g_xT [(size_t)NV*PLANE];   // x transposed: [n][v][c][t]
__device__ float g_sR [(size_t)NV*PLANE];   // result (branches + residual): [n][v][c][t]
__device__ float g_peP[(size_t)V_*32*64];   // pe projection: [v][r(32: q0-15,k0-15)][t]
__device__ float g_part[(size_t)NV*C_];     // per-(n,v,c) sums over t (for SE)
__device__ float g_gmul[N_B*C_];            // per-(n,ch) (1+gate)*bn_scale

// ---------------- helpers ----------------
__device__ __forceinline__ u64 ffma2(u64 a, u64 b, u64 c) {
    u64 d;
    asm("fma.rn.f32x2 %0, %1, %2, %3;" : "=l"(d) : "l"(a), "l"(b), "l"(c));
    return d;
}
__device__ __forceinline__ u64 dup2(float a) {
    u64 r;
    asm("mov.b64 %0, {%1, %1};" : "=l"(r) : "f"(a));
    return r;
}
__device__ __forceinline__ u64 pack2(float lo, float hi) {
    u64 r;
    asm("mov.b64 %0, {%1, %2};" : "=l"(r) : "f"(lo), "f"(hi));
    return r;
}
__device__ __forceinline__ float tanha(float x) {
    float y;
    asm("tanh.approx.f32 %0, %1;" : "=f"(y) : "f"(x));
    return y;
}

// ---------------- K0: transpose x into [n][v][c][t] planes ----------------
__global__ void k_transpose(const float* __restrict__ x) {
    __shared__ float buf[T_*V_];
    int b = blockIdx.x;
    const float* src = x + (size_t)b*(T_*V_);
    for (int i = threadIdx.x; i < T_*V_; i += blockDim.x) buf[i] = src[i];
    __syncthreads();
    int n = b >> 6, c = b & 63;
    for (int i = threadIdx.x; i < T_*V_; i += blockDim.x) {
        int v = i >> 6, t = i & 63;
        g_xT[((size_t)(n*V_ + v))*PLANE + c*T_ + t] = buf[t*V_ + v];
    }
}

// ---------------- K0b: pe projection (per v): peP[r][t] = s_r*(qkvb[r] + W[r]@pe[:,t,v]) ----------------
__global__ void k_peproj(const float* __restrict__ pe, const float* __restrict__ qkvw,
                         const float* __restrict__ qkvb) {
    __shared__ float s_pe[64*64];    // [c][t]
    int v = blockIdx.x, tid = threadIdx.x;
    for (int i = tid; i < 4096; i += 256) {
        int c = i >> 6, t = i & 63;
        s_pe[i] = pe[(size_t)(c*64 + t)*V_ + v];
    }
    __syncthreads();
    int r = tid >> 3;            // 0..31
    int t0 = (tid & 7) * 8;      // 8 t's
    float s = (r < 16) ? 0.70710678118f : 1.f;
    float acc[8];
    #pragma unroll
    for (int i = 0; i < 8; i++) acc[i] = __ldg(&qkvb[r]);
    for (int c = 0; c < 64; c++) {
        float w = __ldg(&qkvw[r*64 + c]);
        #pragma unroll
        for (int i = 0; i < 8; i++) acc[i] += w * s_pe[c*64 + t0 + i];
    }
    float* dst = g_peP + (size_t)v*2048 + r*64 + t0;
    #pragma unroll
    for (int i = 0; i < 8; i++) dst[i] = acc[i] * s;
}

// ---------------- K1: fused attention branch, one block per (n,v) ----------------
// smem floats: x 4096 | w80 5120 | fq/fk/fv/pq/pk 5*1024 | ao 1024 | dbbg 64 | bias 80 | mu 16 | scr 32
#define ATTN_SMEM_BYTES ((size_t)15552*4)
__global__ __launch_bounds__(256, 3)
void k_attn(const float* __restrict__ dbg, const float* __restrict__ dbb,
            const float* __restrict__ qkvw, const float* __restrict__ qkvb,
            const float* __restrict__ aw,  const float* __restrict__ ab) {
    extern __shared__ float sm[];
    float* s_x   = sm;
    float* s_w   = sm + 4096;
    float* s_fq  = sm + 9216;
    float* s_fk  = sm + 10240;
    float* s_fv  = sm + 11264;
    float* s_pq  = sm + 12288;
    float* s_pk  = sm + 13312;
    float* s_ao  = sm + 14336;
    float* s_dbbg= sm + 15360;
    float* s_bias= sm + 15424;
    float* s_mu  = sm + 15504;
    float* s_scr = sm + 15520;

    int tid = threadIdx.x;
    int n = blockIdx.x / V_, v = blockIdx.x % V_;
    const float* xp = g_xT + (size_t)(n*V_ + v)*PLANE;
    float rs = rsqrtf(1.f + EPS_);

    // phase 0: load raw x plane; build fused weights w80 and bias pieces
    for (int idx = tid; idx < PLANE; idx += 256) s_x[idx] = xp[idx];
    if (tid < 64) {
        float g = __ldg(&dbg[tid*V_ + v]) * rs;
        s_dbbg[tid] = __fdividef(__ldg(&dbb[tid*V_ + v]), g);
    }
    // w80 rows: 0-15 fq(=0.7071*g*Wq), 16-31 fk(=g*Wk), 32-47 fv(=g*Wv),
    //           48-63 pq(=0.7071*Wq), 64-79 pk(=Wk)
    for (int idx = tid; idx < 5120; idx += 256) {
        int j = idx >> 6, c = idx & 63;
        int orig; float s;
        if      (j < 16) { orig = j;      s = 0.70710678118f * __ldg(&dbg[c*V_ + v]) * rs; }
        else if (j < 32) { orig = j;      s = __ldg(&dbg[c*V_ + v]) * rs; }
        else if (j < 48) { orig = j + 16; s = __ldg(&dbg[c*V_ + v]) * rs; }
        else if (j < 64) { orig = j - 48; s = 0.70710678118f; }
        else             { orig = j - 48; s = 1.f; }
        s_w[idx] = __ldg(&qkvw[orig*64 + c]) * s;
    }
    if (tid < 48) {
        int orig = (tid < 32) ? tid : tid + 16;
        float s = (tid < 16) ? 0.70710678118f : 1.f;
        s_bias[tid] = __ldg(&qkvb[orig]) * s;
    }
    __syncthreads();

    // phase 0b: bias_j += sum_c w80[j][c] * dbbg[c]   (j < 48)
    if (tid < 48) {
        float b = s_bias[tid];
        const float* wr = s_w + tid*64;
        #pragma unroll 8
        for (int c = 0; c < 64; c++) b += wr[c] * s_dbbg[c];
        s_bias[tid] = b;
    }
    __syncthreads();

    // phase 1: 80-row GEMM on the single x plane; 16 tg x 16 rg, 5 rows per rg
    {
        int tg = tid & 15, rg = tid >> 4;
        int t0 = tg * 4;
        u64 acc[5][2];
        #pragma unroll
        for (int m = 0; m < 5; m++) { acc[m][0] = 0ULL; acc[m][1] = 0ULL; }
        #pragma unroll 4
        for (int c = 0; c < 64; c += 2) {
            u64 xa0 = *(const u64*)&s_x[c*64 + t0];
            u64 xa1 = *(const u64*)&s_x[c*64 + t0 + 2];
            u64 xb0 = *(const u64*)&s_x[(c+1)*64 + t0];
            u64 xb1 = *(const u64*)&s_x[(c+1)*64 + t0 + 2];
            #pragma unroll
            for (int m = 0; m < 5; m++) {
                u64 wp = *(const u64*)&s_w[(rg + 16*m)*64 + c];
                float2 wf = *(float2*)&wp;
                u64 w0 = dup2(wf.x), w1 = dup2(wf.y);
                acc[m][0] = ffma2(w0, xa0, acc[m][0]);
                acc[m][1] = ffma2(w0, xa1, acc[m][1]);
                acc[m][0] = ffma2(w1, xb0, acc[m][0]);
                acc[m][1] = ffma2(w1, xb1, acc[m][1]);
            }
        }
        const float* pePv = g_peP + (size_t)v*2048;
        #pragma unroll
        for (int m = 0; m < 5; m++) {
            float2 lo = *(float2*)&acc[m][0], hi = *(float2*)&acc[m][1];
            float4 o;
            if (m < 3) {
                float b = s_bias[rg + 16*m];
                o.x = lo.x + b; o.y = lo.y + b; o.z = hi.x + b; o.w = hi.y + b;
            } else {
                int pr = (m == 3) ? rg : rg + 16;
                float4 pp = *(const float4*)&pePv[pr*64 + t0];
                o.x = lo.x + pp.x; o.y = lo.y + pp.y; o.z = hi.x + pp.z; o.w = hi.y + pp.w;
            }
            float* dst = (m == 0) ? s_fq : (m == 1) ? s_fk : (m == 2) ? s_fv
                       : (m == 3) ? s_pq : s_pk;
            *(float4*)&dst[rg*64 + t0] = o;
        }
    }
    __syncthreads();

    // phase 2: mu_q = mean_t fq
    if (tid < 16) {
        float s = 0.f;
        #pragma unroll 8
        for (int t = 0; t < 64; t++) s += s_fq[tid*64 + t];
        s_mu[tid] = s * (1.f/64.f);
    }
    __syncthreads();

    // phase 3: attention core, t-pair f32x2 packed, tanh.approx
    {
        int s = tid & 63, hg = tid >> 6;
        #pragma unroll
        for (int hh = 0; hh < 2; hh++) {
            int h = hg + 4*hh;
            int r0 = 2*h, r1 = 2*h + 1;
            float mu0 = s_mu[r0], mu1 = s_mu[r1];
            u64 mu0d = dup2(mu0), mu1d = dup2(mu1);
            u64 fq0d = dup2(s_fq[r0*64 + s] - mu0);
            u64 fq1d = dup2(s_fq[r1*64 + s] - mu1);
            u64 pq0d = dup2(s_pq[r0*64 + s]);
            u64 pq1d = dup2(s_pq[r1*64 + s]);
            const u64* fk0p = (const u64*)&s_fk[r0*64];
            const u64* fk1p = (const u64*)&s_fk[r1*64];
            const u64* pk0p = (const u64*)&s_pk[r0*64];
            const u64* pk1p = (const u64*)&s_pk[r1*64];
            const u64* fv0p = (const u64*)&s_fv[r0*64];
            const u64* fv1p = (const u64*)&s_fv[r1*64];
            u64 a0 = 0ULL, a1 = 0ULL;
            #pragma unroll 4
            for (int tp = 0; tp < 32; tp++) {
                u64 fk0 = fk0p[tp], fk1 = fk1p[tp];
                u64 pk0 = pk0p[tp], pk1 = pk1p[tp];
                u64 lp = ffma2(pq1d, pk1, ffma2(pq0d, pk0, 0ULL));
                u64 pw = ffma2(fq1d, fk1, ffma2(fq0d, fk0, lp));
                u64 un = ffma2(mu1d, fk1, ffma2(mu0d, fk0, lp));
                float2 pwf = *(float2*)&pw, unf = *(float2*)&un;
                float w0 = tanha(pwf.x) + tanha(unf.x);
                float w1 = tanha(pwf.y) + tanha(unf.y);
                u64 w2 = pack2(w0, w1);
                a0 = ffma2(w2, fv0p[tp], a0);
                a1 = ffma2(w2, fv1p[tp], a1);
            }
            float2 A0 = *(float2*)&a0, A1 = *(float2*)&a1;
            s_ao[r0*64 + s] = A0.x + A0.y;
            s_ao[r1*64 + s] = A1.x + A1.y;
        }
    }
    __syncthreads();

    // phase 4: attn output projection (16x16) + residual + SE partials (ch 48..63)
    {
        int t = tid & 63, og = tid >> 6;
        const float* xres = g_xT + (size_t)(n*V_ + v)*PLANE + 48*64;
        float*       outp = g_sR + (size_t)(n*V_ + v)*PLANE + 48*64;
        int half = t >> 5;
        #pragma unroll
        for (int i = 0; i < 4; i++) {
            int o = og*4 + i;
            float acc = __ldg(&ab[o]);
            #pragma unroll
            for (int c = 0; c < 16; c++) acc += __ldg(&aw[o*16 + c]) * s_ao[c*64 + t];
            float res = acc + xres[o*64 + t];
            outp[o*64 + t] = res;
            float vsum = res;
            #pragma unroll
            for (int off = 16; off > 0; off >>= 1)
                vsum += __shfl_down_sync(0xffffffffu, vsum, off);
            if ((t & 31) == 0) s_scr[o*2 + half] = vsum;
        }
    }
    __syncthreads();
    if (tid < 16)
        g_part[(size_t)(n*V_ + v)*64 + 48 + tid] = s_scr[2*tid] + s_scr[2*tid+1];
}

// ---------------- K2: TCN branch, 2 planes per block ----------------
#define TCN_PL 2
#define TCN_THREADS (192*TCN_PL)
#define TCN_SMEM_BYTES ((size_t)(24*580*8 + TCN_PL*64*72*4))
__global__ __launch_bounds__(TCN_THREADS, 1)
void k_tcn(const float* __restrict__ tw, const float* __restrict__ tb,
           const float* __restrict__ tbg, const float* __restrict__ tbb) {
    extern __shared__ float smr[];
    float2* s_w2 = (float2*)smr;                 // 24*580 float2
    float*  s_xs = smr + 24*580*2;               // TCN_PL * 64*72 floats
    int tid = threadIdx.x;
    int plane0 = blockIdx.x * TCN_PL;

    for (int idx = tid; idx < 24*576; idx += TCN_THREADS) {
        int op = idx / 576, j = idx - op*576;
        float a = tw[(2*op  )*576 + j];
        float b = tw[(2*op+1)*576 + j];
        s_w2[op*580 + j] = make_float2(a, b);
    }
    for (int idx = tid; idx < TCN_PL*64*72; idx += TCN_THREADS) {
        int pl = idx / 4608, rem = idx - pl*4608;
        int c = rem / 72, j = rem - c*72;
        int t = j - 4;
        s_xs[idx] = (t >= 0 && t < T_)
                  ? g_xT[(size_t)(plane0 + pl)*PLANE + c*T_ + t] : 0.f;
    }
    __syncthreads();

    int pl = tid / 192, r = tid - pl*192;
    int op = r >> 3, tg = r & 7;
    int t0 = tg * 8;
    const float* xs = s_xs + pl*4608;

    u64 acc2[8];
    #pragma unroll
    for (int i = 0; i < 8; i++) acc2[i] = 0ULL;

    for (int c = 0; c < 64; c++) {
        const float* xr = xs + c*72 + t0;
        u64 xd[16];
        #pragma unroll
        for (int i = 0; i < 16; i++) xd[i] = dup2(xr[i]);
        const float2* wp = s_w2 + op*580 + c*9;
        #pragma unroll
        for (int k = 0; k < 9; k++) {
            u64 w2 = *(const u64*)(wp + k);
            #pragma unroll
            for (int i = 0; i < 8; i++) acc2[i] = ffma2(w2, xd[i + k], acc2[i]);
        }
    }

    int o0 = 2*op, o1 = o0 + 1;
    float rsq = rsqrtf(1.f + EPS_);
    float ts0 = __ldg(&tbg[o0]) * rsq, ts1 = __ldg(&tbg[o1]) * rsq;
    float cb0 = __ldg(&tb[o0]) * ts0 + __ldg(&tbb[o0]);
    float cb1 = __ldg(&tb[o1]) * ts1 + __ldg(&tbb[o1]);
    float* out0 = g_sR + (size_t)(plane0 + pl)*PLANE + o0*T_;
    float* out1 = out0 + T_;
    float s0 = 0.f, s1 = 0.f;
    #pragma unroll
    for (int i = 0; i < 8; i++) {
        float2 p = *(float2*)&acc2[i];
        int t = t0 + i;
        float v0 = p.x*ts0 + cb0 + xs[o0*72 + 4 + t];
        float v1 = p.y*ts1 + cb1 + xs[o1*72 + 4 + t];
        out0[t] = v0; out1[t] = v1;
        s0 += v0; s1 += v1;
    }
    #pragma unroll
    for (int off = 4; off > 0; off >>= 1) {
        s0 += __shfl_down_sync(0xffffffffu, s0, off, 8);
        s1 += __shfl_down_sync(0xffffffffu, s1, off, 8);
    }
    if (tg == 0) {
        g_part[(size_t)(plane0 + pl)*64 + o0] = s0;
        g_part[(size_t)(plane0 + pl)*64 + o1] = s1;
    }
}

// ---------------- K3: SE gate MLP from partials, one block per n ----------------
__global__ void k_se(const float* __restrict__ f1w, const float* __restrict__ f1b,
                     const float* __restrict__ f2w, const float* __restrict__ f2b,
                     const float* __restrict__ bng) {
    __shared__ float s_red[4][64];
    __shared__ float s_se[64];
    __shared__ float s_h1[32];
    int n = blockIdx.x, tid = threadIdx.x;
    int c = tid & 63, vg = tid >> 6;
    float s = 0.f;
    for (int v = vg; v < V_; v += 4) s += g_part[(size_t)(n*V_ + v)*64 + c];
    s_red[vg][c] = s;
    __syncthreads();
    if (tid < 64) {
        s_se[tid] = (s_red[0][tid] + s_red[1][tid] + s_red[2][tid] + s_red[3][tid])
                    * (1.f/1600.f);
    }
    __syncthreads();
    if (tid < 32) {
        float a = f1b[tid];
        #pragma unroll
        for (int j = 0; j < 64; j++) a += f1w[tid*64 + j] * s_se[j];
        s_h1[tid] = fmaxf(a, 0.f);
    }
    __syncthreads();
    if (tid < 64) {
        float a = f2b[tid];
        #pragma unroll
        for (int j = 0; j < 32; j++) a += f2w[tid*32 + j] * s_h1[j];
        float sg = __fdividef(1.f, 1.f + __expf(-a));
        g_gmul[n*64 + tid] = (1.f + sg) * bng[tid] * rsqrtf(1.f + EPS_);
    }
}

// ---------------- K4: gate * BN * ReLU + transpose back to (N,C,T,V) ----------------
__global__ void k_final(const float* __restrict__ bnb, float* __restrict__ out) {
    __shared__ float s_buf[25*65];
    int b = blockIdx.x;
    int n = b >> 6, c = b & 63;
    const float* base = g_sR + (size_t)n*V_*PLANE + c*T_;
    for (int idx = threadIdx.x; idx < T_*V_; idx += 256) {
        int v = idx >> 6, t = idx & 63;
        s_buf[v*65 + t] = base[(size_t)v*PLANE + t];
    }
    __syncthreads();
    float m = g_gmul[n*64 + c], bb = bnb[c];
    float* op = out + (size_t)(n*64 + c)*(T_*V_);
    for (int idx = threadIdx.x; idx < T_*V_; idx += 256) {
        int t = idx / 25, v = idx - t*25;
        float val = s_buf[v*65 + t] * m + bb;
        op[idx] = fmaxf(val, 0.f);
    }
}

// ---------------- launcher ----------------
extern "C" void kernel_launch(void* const* d_in, const int* in_sizes, int n_in,
                              void* d_out, int out_size) {
    (void)in_sizes; (void)n_in; (void)out_size;
    const float* x    = (const float*)d_in[0];
    const float* pe   = (const float*)d_in[1];
    const float* dbg  = (const float*)d_in[2];
    const float* dbb  = (const float*)d_in[3];
    const float* qkvw = (const float*)d_in[4];
    const float* qkvb = (const float*)d_in[5];
    const float* aw   = (const float*)d_in[6];
    const float* ab   = (const float*)d_in[7];
    const float* tw   = (const float*)d_in[8];
    const float* tb   = (const float*)d_in[9];
    const float* tbg  = (const float*)d_in[10];
    const float* tbb  = (const float*)d_in[11];
    const float* f1w  = (const float*)d_in[12];
    const float* f1b  = (const float*)d_in[13];
    const float* f2w  = (const float*)d_in[14];
    const float* f2b  = (const float*)d_in[15];
    const float* bng  = (const float*)d_in[16];
    const float* bnb  = (const float*)d_in[17];

    cudaFuncSetAttribute(k_attn, cudaFuncAttributeMaxDynamicSharedMemorySize, (int)ATTN_SMEM_BYTES);
    cudaFuncSetAttribute(k_tcn,  cudaFuncAttributeMaxDynamicSharedMemorySize, (int)TCN_SMEM_BYTES);

    // launch order chosen so position 3 (ncu capture slot) = k_tcn
    k_transpose<<<N_B*C_, 256>>>(x);
    k_peproj<<<V_, 256>>>(pe, qkvw, qkvb);
    k_attn<<<NV, 256, ATTN_SMEM_BYTES>>>(dbg, dbb, qkvw, qkvb, aw, ab);
    k_tcn <<<NV/TCN_PL, TCN_THREADS, TCN_SMEM_BYTES>>>(tw, tb, tbg, tbb);
    k_se  <<<N_B, 256>>>(f1w, f1b, f2w, f2b, bng);
    k_final<<<N_B*C_, 256>>>(bnb, (float*)d_out);
}

// round 9
// speedup vs baseline: 1.4461x; 1.0377x over previous
#include <cuda_runtime.h>
#include <math.h>

// ---------------- problem constants ----------------
#define N_B   64
#define C_    64
#define T_    64
#define V_    25
#define NV    (N_B*V_)       // 1600 sequences
#define PLANE (C_*T_)        // 4096 floats per (n,v) plane
#define EPS_  1e-5f

typedef unsigned long long u64;

// ---------------- device scratch (no allocations allowed) ----------------
__device__ float g_xT [(size_t)NV*PLANE];   // x transposed: [n][v][c][t]
__device__ float g_sR [(size_t)NV*PLANE];   // result (branches + residual): [n][v][c][t]
__device__ float g_peP[(size_t)V_*32*64];   // pe projection: [v][r(32: q0-15,k0-15)][t]
__device__ float g_part[(size_t)NV*C_];     // per-(n,v,c) sums over t (for SE)
__device__ float g_gmul[N_B*C_];            // per-(n,ch) (1+gate)*bn_scale

// ---------------- helpers ----------------
__device__ __forceinline__ u64 ffma2(u64 a, u64 b, u64 c) {
    u64 d;
    asm("fma.rn.f32x2 %0, %1, %2, %3;" : "=l"(d) : "l"(a), "l"(b), "l"(c));
    return d;
}
__device__ __forceinline__ u64 dup2(float a) {
    u64 r;
    asm("mov.b64 %0, {%1, %1};" : "=l"(r) : "f"(a));
    return r;
}
__device__ __forceinline__ u64 pack2(float lo, float hi) {
    u64 r;
    asm("mov.b64 %0, {%1, %2};" : "=l"(r) : "f"(lo), "f"(hi));
    return r;
}
__device__ __forceinline__ float tanha(float x) {
    float y;
    asm("tanh.approx.f32 %0, %1;" : "=f"(y) : "f"(x));
    return y;
}

// ---------------- K0: transpose x into [n][v][c][t] planes ----------------
__global__ void k_transpose(const float* __restrict__ x) {
    __shared__ float buf[T_*V_];
    int b = blockIdx.x;
    const float* src = x + (size_t)b*(T_*V_);
    for (int i = threadIdx.x; i < T_*V_; i += blockDim.x) buf[i] = src[i];
    __syncthreads();
    int n = b >> 6, c = b & 63;
    for (int i = threadIdx.x; i < T_*V_; i += blockDim.x) {
        int v = i >> 6, t = i & 63;
        g_xT[((size_t)(n*V_ + v))*PLANE + c*T_ + t] = buf[t*V_ + v];
    }
}

// ---------------- K0b: pe projection (per v): peP[r][t] = s_r*(qkvb[r] + W[r]@pe[:,t,v]) ----------------
__global__ void k_peproj(const float* __restrict__ pe, const float* __restrict__ qkvw,
                         const float* __restrict__ qkvb) {
    __shared__ float s_pe[64*64];    // [c][t]
    int v = blockIdx.x, tid = threadIdx.x;
    for (int i = tid; i < 4096; i += 256) {
        int c = i >> 6, t = i & 63;
        s_pe[i] = pe[(size_t)(c*64 + t)*V_ + v];
    }
    __syncthreads();
    int r = tid >> 3;            // 0..31
    int t0 = (tid & 7) * 8;      // 8 t's
    float s = (r < 16) ? 0.70710678118f : 1.f;
    float acc[8];
    #pragma unroll
    for (int i = 0; i < 8; i++) acc[i] = __ldg(&qkvb[r]);
    for (int c = 0; c < 64; c++) {
        float w = __ldg(&qkvw[r*64 + c]);
        #pragma unroll
        for (int i = 0; i < 8; i++) acc[i] += w * s_pe[c*64 + t0 + i];
    }
    float* dst = g_peP + (size_t)v*2048 + r*64 + t0;
    #pragma unroll
    for (int i = 0; i < 8; i++) dst[i] = acc[i] * s;
}

// ---------------- K1: fused attention branch, one block per (n,v) ----------------
// smem floats: x 4096 | w80 5120 | fq/fk/fv/pq/pk 5*1024 | ao 1024 | dbbg 64 | bias 80 | mu 16 | scr 32
#define ATTN_SMEM_BYTES ((size_t)15552*4)
__global__ __launch_bounds__(256, 3)
void k_attn(const float* __restrict__ dbg, const float* __restrict__ dbb,
            const float* __restrict__ qkvw, const float* __restrict__ qkvb,
            const float* __restrict__ aw,  const float* __restrict__ ab) {
    extern __shared__ float sm[];
    float* s_x   = sm;
    float* s_w   = sm + 4096;
    float* s_fq  = sm + 9216;
    float* s_fk  = sm + 10240;
    float* s_fv  = sm + 11264;
    float* s_pq  = sm + 12288;
    float* s_pk  = sm + 13312;
    float* s_ao  = sm + 14336;
    float* s_dbbg= sm + 15360;
    float* s_bias= sm + 15424;
    float* s_mu  = sm + 15504;
    float* s_scr = sm + 15520;

    int tid = threadIdx.x;
    int n = blockIdx.x / V_, v = blockIdx.x % V_;
    const float* xp = g_xT + (size_t)(n*V_ + v)*PLANE;
    float rs = rsqrtf(1.f + EPS_);

    // phase 0: load raw x plane; build fused weights w80 and bias pieces
    for (int idx = tid; idx < PLANE; idx += 256) s_x[idx] = xp[idx];
    if (tid < 64) {
        float g = __ldg(&dbg[tid*V_ + v]) * rs;
        s_dbbg[tid] = __fdividef(__ldg(&dbb[tid*V_ + v]), g);
    }
    // w80 rows: 0-15 fq(=0.7071*g*Wq), 16-31 fk(=g*Wk), 32-47 fv(=g*Wv),
    //           48-63 pq(=0.7071*Wq), 64-79 pk(=Wk)
    for (int idx = tid; idx < 5120; idx += 256) {
        int j = idx >> 6, c = idx & 63;
        int orig; float s;
        if      (j < 16) { orig = j;      s = 0.70710678118f * __ldg(&dbg[c*V_ + v]) * rs; }
        else if (j < 32) { orig = j;      s = __ldg(&dbg[c*V_ + v]) * rs; }
        else if (j < 48) { orig = j + 16; s = __ldg(&dbg[c*V_ + v]) * rs; }
        else if (j < 64) { orig = j - 48; s = 0.70710678118f; }
        else             { orig = j - 48; s = 1.f; }
        s_w[idx] = __ldg(&qkvw[orig*64 + c]) * s;
    }
    if (tid < 48) {
        int orig = (tid < 32) ? tid : tid + 16;
        float s = (tid < 16) ? 0.70710678118f : 1.f;
        s_bias[tid] = __ldg(&qkvb[orig]) * s;
    }
    __syncthreads();

    // phase 0b: bias_j += sum_c w80[j][c] * dbbg[c]   (j < 48)
    if (tid < 48) {
        float b = s_bias[tid];
        const float* wr = s_w + tid*64;
        #pragma unroll 8
        for (int c = 0; c < 64; c++) b += wr[c] * s_dbbg[c];
        s_bias[tid] = b;
    }
    __syncthreads();

    // phase 1: 80-row GEMM on the single x plane; 16 tg x 16 rg, 5 rows per rg
    {
        int tg = tid & 15, rg = tid >> 4;
        int t0 = tg * 4;
        u64 acc[5][2];
        #pragma unroll
        for (int m = 0; m < 5; m++) { acc[m][0] = 0ULL; acc[m][1] = 0ULL; }
        #pragma unroll 4
        for (int c = 0; c < 64; c += 2) {
            u64 xa0 = *(const u64*)&s_x[c*64 + t0];
            u64 xa1 = *(const u64*)&s_x[c*64 + t0 + 2];
            u64 xb0 = *(const u64*)&s_x[(c+1)*64 + t0];
            u64 xb1 = *(const u64*)&s_x[(c+1)*64 + t0 + 2];
            #pragma unroll
            for (int m = 0; m < 5; m++) {
                u64 wp = *(const u64*)&s_w[(rg + 16*m)*64 + c];
                float2 wf = *(float2*)&wp;
                u64 w0 = dup2(wf.x), w1 = dup2(wf.y);
                acc[m][0] = ffma2(w0, xa0, acc[m][0]);
                acc[m][1] = ffma2(w0, xa1, acc[m][1]);
                acc[m][0] = ffma2(w1, xb0, acc[m][0]);
                acc[m][1] = ffma2(w1, xb1, acc[m][1]);
            }
        }
        const float* pePv = g_peP + (size_t)v*2048;
        #pragma unroll
        for (int m = 0; m < 5; m++) {
            float2 lo = *(float2*)&acc[m][0], hi = *(float2*)&acc[m][1];
            float4 o;
            if (m < 3) {
                float b = s_bias[rg + 16*m];
                o.x = lo.x + b; o.y = lo.y + b; o.z = hi.x + b; o.w = hi.y + b;
            } else {
                int pr = (m == 3) ? rg : rg + 16;
                float4 pp = *(const float4*)&pePv[pr*64 + t0];
                o.x = lo.x + pp.x; o.y = lo.y + pp.y; o.z = hi.x + pp.z; o.w = hi.y + pp.w;
            }
            float* dst = (m == 0) ? s_fq : (m == 1) ? s_fk : (m == 2) ? s_fv
                       : (m == 3) ? s_pq : s_pk;
            *(float4*)&dst[rg*64 + t0] = o;
        }
    }
    __syncthreads();

    // phase 2: mu_q = mean_t fq
    if (tid < 16) {
        float s = 0.f;
        #pragma unroll 8
        for (int t = 0; t < 64; t++) s += s_fq[tid*64 + t];
        s_mu[tid] = s * (1.f/64.f);
    }
    __syncthreads();

    // phase 3: attention core, t-pair f32x2 packed, tanh.approx
    {
        int s = tid & 63, hg = tid >> 6;
        #pragma unroll
        for (int hh = 0; hh < 2; hh++) {
            int h = hg + 4*hh;
            int r0 = 2*h, r1 = 2*h + 1;
            float mu0 = s_mu[r0], mu1 = s_mu[r1];
            u64 mu0d = dup2(mu0), mu1d = dup2(mu1);
            u64 fq0d = dup2(s_fq[r0*64 + s] - mu0);
            u64 fq1d = dup2(s_fq[r1*64 + s] - mu1);
            u64 pq0d = dup2(s_pq[r0*64 + s]);
            u64 pq1d = dup2(s_pq[r1*64 + s]);
            const u64* fk0p = (const u64*)&s_fk[r0*64];
            const u64* fk1p = (const u64*)&s_fk[r1*64];
            const u64* pk0p = (const u64*)&s_pk[r0*64];
            const u64* pk1p = (const u64*)&s_pk[r1*64];
            const u64* fv0p = (const u64*)&s_fv[r0*64];
            const u64* fv1p = (const u64*)&s_fv[r1*64];
            u64 a0 = 0ULL, a1 = 0ULL;
            #pragma unroll 4
            for (int tp = 0; tp < 32; tp++) {
                u64 fk0 = fk0p[tp], fk1 = fk1p[tp];
                u64 pk0 = pk0p[tp], pk1 = pk1p[tp];
                u64 lp = ffma2(pq1d, pk1, ffma2(pq0d, pk0, 0ULL));
                u64 pw = ffma2(fq1d, fk1, ffma2(fq0d, fk0, lp));
                u64 un = ffma2(mu1d, fk1, ffma2(mu0d, fk0, lp));
                float2 pwf = *(float2*)&pw, unf = *(float2*)&un;
                float w0 = tanha(pwf.x) + tanha(unf.x);
                float w1 = tanha(pwf.y) + tanha(unf.y);
                u64 w2 = pack2(w0, w1);
                a0 = ffma2(w2, fv0p[tp], a0);
                a1 = ffma2(w2, fv1p[tp], a1);
            }
            float2 A0 = *(float2*)&a0, A1 = *(float2*)&a1;
            s_ao[r0*64 + s] = A0.x + A0.y;
            s_ao[r1*64 + s] = A1.x + A1.y;
        }
    }
    __syncthreads();

    // phase 4: attn output projection (16x16) + residual + SE partials (ch 48..63)
    {
        int t = tid & 63, og = tid >> 6;
        const float* xres = g_xT + (size_t)(n*V_ + v)*PLANE + 48*64;
        float*       outp = g_sR + (size_t)(n*V_ + v)*PLANE + 48*64;
        int half = t >> 5;
        #pragma unroll
        for (int i = 0; i < 4; i++) {
            int o = og*4 + i;
            float acc = __ldg(&ab[o]);
            #pragma unroll
            for (int c = 0; c < 16; c++) acc += __ldg(&aw[o*16 + c]) * s_ao[c*64 + t];
            float res = acc + xres[o*64 + t];
            outp[o*64 + t] = res;
            float vsum = res;
            #pragma unroll
            for (int off = 16; off > 0; off >>= 1)
                vsum += __shfl_down_sync(0xffffffffu, vsum, off);
            if ((t & 31) == 0) s_scr[o*2 + half] = vsum;
        }
    }
    __syncthreads();
    if (tid < 16)
        g_part[(size_t)(n*V_ + v)*64 + 48 + tid] = s_scr[2*tid] + s_scr[2*tid+1];
}

// ---------------- K2: TCN branch, 4 planes per block ----------------
// 768 threads = 4 planes x (24 o-pairs x 8 t-groups). FFMA2-packed over o-pair.
// x loaded via float4 (LDS.128) — 4 vector loads per (c,thread), not 16 scalars.
#define TCN_PL 4
#define TCN_THREADS (192*TCN_PL)
#define TCN_SMEM_BYTES ((size_t)(24*580*8 + TCN_PL*64*72*4))
__global__ __launch_bounds__(TCN_THREADS, 1)
void k_tcn(const float* __restrict__ tw, const float* __restrict__ tb,
           const float* __restrict__ tbg, const float* __restrict__ tbb) {
    extern __shared__ float smr[];
    float2* s_w2 = (float2*)smr;                 // 24*580 float2
    float*  s_xs = smr + 24*580*2;               // TCN_PL * 64*72 floats
    int tid = threadIdx.x;
    int plane0 = blockIdx.x * TCN_PL;

    for (int idx = tid; idx < 24*576; idx += TCN_THREADS) {
        int op = idx / 576, j = idx - op*576;
        float a = tw[(2*op  )*576 + j];
        float b = tw[(2*op+1)*576 + j];
        s_w2[op*580 + j] = make_float2(a, b);
    }
    for (int idx = tid; idx < TCN_PL*64*72; idx += TCN_THREADS) {
        int pl = idx / 4608, rem = idx - pl*4608;
        int c = rem / 72, j = rem - c*72;
        int t = j - 4;
        s_xs[idx] = (t >= 0 && t < T_)
                  ? g_xT[(size_t)(plane0 + pl)*PLANE + c*T_ + t] : 0.f;
    }
    __syncthreads();

    int pl = tid / 192, r = tid - pl*192;
    int op = r >> 3, tg = r & 7;
    int t0 = tg * 8;
    const float* xs = s_xs + pl*4608;

    u64 acc2[8];
    #pragma unroll
    for (int i = 0; i < 8; i++) acc2[i] = 0ULL;

    for (int c = 0; c < 64; c++) {
        const float* xr = xs + c*72 + t0;
        float4 q0 = *(const float4*)(xr);
        float4 q1 = *(const float4*)(xr + 4);
        float4 q2 = *(const float4*)(xr + 8);
        float4 q3 = *(const float4*)(xr + 12);
        u64 xd[16];
        xd[0]=dup2(q0.x); xd[1]=dup2(q0.y); xd[2]=dup2(q0.z); xd[3]=dup2(q0.w);
        xd[4]=dup2(q1.x); xd[5]=dup2(q1.y); xd[6]=dup2(q1.z); xd[7]=dup2(q1.w);
        xd[8]=dup2(q2.x); xd[9]=dup2(q2.y); xd[10]=dup2(q2.z); xd[11]=dup2(q2.w);
        xd[12]=dup2(q3.x); xd[13]=dup2(q3.y); xd[14]=dup2(q3.z); xd[15]=dup2(q3.w);
        const float2* wp = s_w2 + op*580 + c*9;
        #pragma unroll
        for (int k = 0; k < 9; k++) {
            u64 w2 = *(const u64*)(wp + k);
            #pragma unroll
            for (int i = 0; i < 8; i++) acc2[i] = ffma2(w2, xd[i + k], acc2[i]);
        }
    }

    int o0 = 2*op, o1 = o0 + 1;
    float rsq = rsqrtf(1.f + EPS_);
    float ts0 = __ldg(&tbg[o0]) * rsq, ts1 = __ldg(&tbg[o1]) * rsq;
    float cb0 = __ldg(&tb[o0]) * ts0 + __ldg(&tbb[o0]);
    float cb1 = __ldg(&tb[o1]) * ts1 + __ldg(&tbb[o1]);
    float* out0 = g_sR + (size_t)(plane0 + pl)*PLANE + o0*T_;
    float* out1 = out0 + T_;
    float s0 = 0.f, s1 = 0.f;
    #pragma unroll
    for (int i = 0; i < 8; i++) {
        float2 p = *(float2*)&acc2[i];
        int t = t0 + i;
        float v0 = p.x*ts0 + cb0 + xs[o0*72 + 4 + t];
        float v1 = p.y*ts1 + cb1 + xs[o1*72 + 4 + t];
        out0[t] = v0; out1[t] = v1;
        s0 += v0; s1 += v1;
    }
    #pragma unroll
    for (int off = 4; off > 0; off >>= 1) {
        s0 += __shfl_down_sync(0xffffffffu, s0, off, 8);
        s1 += __shfl_down_sync(0xffffffffu, s1, off, 8);
    }
    if (tg == 0) {
        g_part[(size_t)(plane0 + pl)*64 + o0] = s0;
        g_part[(size_t)(plane0 + pl)*64 + o1] = s1;
    }
}

// ---------------- K3: SE gate MLP from partials, one block per n ----------------
__global__ void k_se(const float* __restrict__ f1w, const float* __restrict__ f1b,
                     const float* __restrict__ f2w, const float* __restrict__ f2b,
                     const float* __restrict__ bng) {
    __shared__ float s_red[4][64];
    __shared__ float s_se[64];
    __shared__ float s_h1[32];
    int n = blockIdx.x, tid = threadIdx.x;
    int c = tid & 63, vg = tid >> 6;
    float s = 0.f;
    for (int v = vg; v < V_; v += 4) s += g_part[(size_t)(n*V_ + v)*64 + c];
    s_red[vg][c] = s;
    __syncthreads();
    if (tid < 64) {
        s_se[tid] = (s_red[0][tid] + s_red[1][tid] + s_red[2][tid] + s_red[3][tid])
                    * (1.f/1600.f);
    }
    __syncthreads();
    if (tid < 32) {
        float a = f1b[tid];
        #pragma unroll
        for (int j = 0; j < 64; j++) a += f1w[tid*64 + j] * s_se[j];
        s_h1[tid] = fmaxf(a, 0.f);
    }
    __syncthreads();
    if (tid < 64) {
        float a = f2b[tid];
        #pragma unroll
        for (int j = 0; j < 32; j++) a += f2w[tid*32 + j] * s_h1[j];
        float sg = __fdividef(1.f, 1.f + __expf(-a));
        g_gmul[n*64 + tid] = (1.f + sg) * bng[tid] * rsqrtf(1.f + EPS_);
    }
}

// ---------------- K4: gate * BN * ReLU + transpose back to (N,C,T,V) ----------------
__global__ void k_final(const float* __restrict__ bnb, float* __restrict__ out) {
    __shared__ float s_buf[25*65];
    int b = blockIdx.x;
    int n = b >> 6, c = b & 63;
    const float* base = g_sR + (size_t)n*V_*PLANE + c*T_;
    for (int idx = threadIdx.x; idx < T_*V_; idx += 256) {
        int v = idx >> 6, t = idx & 63;
        s_buf[v*65 + t] = base[(size_t)v*PLANE + t];
    }
    __syncthreads();
    float m = g_gmul[n*64 + c], bb = bnb[c];
    float* op = out + (size_t)(n*64 + c)*(T_*V_);
    for (int idx = threadIdx.x; idx < T_*V_; idx += 256) {
        int t = idx / 25, v = idx - t*25;
        float val = s_buf[v*65 + t] * m + bb;
        op[idx] = fmaxf(val, 0.f);
    }
}

// ---------------- launcher ----------------
extern "C" void kernel_launch(void* const* d_in, const int* in_sizes, int n_in,
                              void* d_out, int out_size) {
    (void)in_sizes; (void)n_in; (void)out_size;
    const float* x    = (const float*)d_in[0];
    const float* pe   = (const float*)d_in[1];
    const float* dbg  = (const float*)d_in[2];
    const float* dbb  = (const float*)d_in[3];
    const float* qkvw = (const float*)d_in[4];
    const float* qkvb = (const float*)d_in[5];
    const float* aw   = (const float*)d_in[6];
    const float* ab   = (const float*)d_in[7];
    const float* tw   = (const float*)d_in[8];
    const float* tb   = (const float*)d_in[9];
    const float* tbg  = (const float*)d_in[10];
    const float* tbb  = (const float*)d_in[11];
    const float* f1w  = (const float*)d_in[12];
    const float* f1b  = (const float*)d_in[13];
    const float* f2w  = (const float*)d_in[14];
    const float* f2b  = (const float*)d_in[15];
    const float* bng  = (const float*)d_in[16];
    const float* bnb  = (const float*)d_in[17];

    cudaFuncSetAttribute(k_attn, cudaFuncAttributeMaxDynamicSharedMemorySize, (int)ATTN_SMEM_BYTES);
    cudaFuncSetAttribute(k_tcn,  cudaFuncAttributeMaxDynamicSharedMemorySize, (int)TCN_SMEM_BYTES);

    // launch order kept identical so ncu recaptures k_tcn
    k_transpose<<<N_B*C_, 256>>>(x);
    k_peproj<<<V_, 256>>>(pe, qkvw, qkvb);
    k_attn<<<NV, 256, ATTN_SMEM_BYTES>>>(dbg, dbb, qkvw, qkvb, aw, ab);
    k_tcn <<<NV/TCN_PL, TCN_THREADS, TCN_SMEM_BYTES>>>(tw, tb, tbg, tbb);
    k_se  <<<N_B, 256>>>(f1w, f1b, f2w, f2b, bng);
    k_final<<<N_B*C_, 256>>>(bnb, (float*)d_out);
}

// round 11
// speedup vs baseline: 1.4579x; 1.0082x over previous
#include <cuda_runtime.h>
#include <math.h>

// ---------------- problem constants ----------------
#define N_B   64
#define C_    64
#define T_    64
#define V_    25
#define NV    (N_B*V_)       // 1600 sequences
#define PLANE (C_*T_)        // 4096 floats per (n,v) plane
#define EPS_  1e-5f

typedef unsigned long long u64;

// ---------------- device scratch (no allocations allowed) ----------------
__device__ float g_xT [(size_t)NV*PLANE];   // x transposed: [n][v][c][t]
__device__ float g_sR [(size_t)NV*PLANE];   // result (branches + residual): [n][v][c][t]
__device__ float g_peP[(size_t)V_*32*64];   // pe projection: [v][r(32: q0-15,k0-15)][t]
__device__ float g_part[(size_t)NV*C_];     // per-(n,v,c) sums over t (for SE)
__device__ float g_gmul[N_B*C_];            // per-(n,ch) (1+gate)*bn_scale

// ---------------- helpers ----------------
__device__ __forceinline__ u64 ffma2(u64 a, u64 b, u64 c) {
    u64 d;
    asm("fma.rn.f32x2 %0, %1, %2, %3;" : "=l"(d) : "l"(a), "l"(b), "l"(c));
    return d;
}
__device__ __forceinline__ u64 dup2(float a) {
    u64 r;
    asm("mov.b64 %0, {%1, %1};" : "=l"(r) : "f"(a));
    return r;
}
__device__ __forceinline__ u64 pack2(float lo, float hi) {
    u64 r;
    asm("mov.b64 %0, {%1, %2};" : "=l"(r) : "f"(lo), "f"(hi));
    return r;
}
__device__ __forceinline__ float tanha(float x) {
    float y;
    asm("tanh.approx.f32 %0, %1;" : "=f"(y) : "f"(x));
    return y;
}

// ---------------- K0: transpose x into [n][v][c][t] planes ----------------
__global__ void k_transpose(const float* __restrict__ x) {
    __shared__ float buf[T_*V_];
    int b = blockIdx.x;
    const float* src = x + (size_t)b*(T_*V_);
    for (int i = threadIdx.x; i < T_*V_; i += blockDim.x) buf[i] = src[i];
    __syncthreads();
    int n = b >> 6, c = b & 63;
    for (int i = threadIdx.x; i < T_*V_; i += blockDim.x) {
        int v = i >> 6, t = i & 63;
        g_xT[((size_t)(n*V_ + v))*PLANE + c*T_ + t] = buf[t*V_ + v];
    }
}

// ---------------- K0b: pe projection (per v): peP[r][t] = s_r*(qkvb[r] + W[r]@pe[:,t,v]) ----------------
__global__ void k_peproj(const float* __restrict__ pe, const float* __restrict__ qkvw,
                         const float* __restrict__ qkvb) {
    __shared__ float s_pe[64*64];    // [c][t]
    int v = blockIdx.x, tid = threadIdx.x;
    for (int i = tid; i < 4096; i += 256) {
        int c = i >> 6, t = i & 63;
        s_pe[i] = pe[(size_t)(c*64 + t)*V_ + v];
    }
    __syncthreads();
    int r = tid >> 3;            // 0..31
    int t0 = (tid & 7) * 8;      // 8 t's
    float s = (r < 16) ? 0.70710678118f : 1.f;
    float acc[8];
    #pragma unroll
    for (int i = 0; i < 8; i++) acc[i] = __ldg(&qkvb[r]);
    for (int c = 0; c < 64; c++) {
        float w = __ldg(&qkvw[r*64 + c]);
        #pragma unroll
        for (int i = 0; i < 8; i++) acc[i] += w * s_pe[c*64 + t0 + i];
    }
    float* dst = g_peP + (size_t)v*2048 + r*64 + t0;
    #pragma unroll
    for (int i = 0; i < 8; i++) dst[i] = acc[i] * s;
}

// ---------------- K1: fused attention branch, one block per (n,v) ----------------
// smem floats: x 4096 | w80 5120 | fq/fk/fv/pq/pk 5*1024 | ao 1024 | dbbg 64 | bias 80 | mu 16 | scr 32
#define ATTN_SMEM_BYTES ((size_t)15552*4)
__global__ __launch_bounds__(256, 3)
void k_attn(const float* __restrict__ dbg, const float* __restrict__ dbb,
            const float* __restrict__ qkvw, const float* __restrict__ qkvb,
            const float* __restrict__ aw,  const float* __restrict__ ab) {
    extern __shared__ float sm[];
    float* s_x   = sm;
    float* s_w   = sm + 4096;
    float* s_fq  = sm + 9216;
    float* s_fk  = sm + 10240;
    float* s_fv  = sm + 11264;
    float* s_pq  = sm + 12288;
    float* s_pk  = sm + 13312;
    float* s_ao  = sm + 14336;
    float* s_dbbg= sm + 15360;
    float* s_bias= sm + 15424;
    float* s_mu  = sm + 15504;
    float* s_scr = sm + 15520;

    int tid = threadIdx.x;
    int n = blockIdx.x / V_, v = blockIdx.x % V_;
    const float* xp = g_xT + (size_t)(n*V_ + v)*PLANE;
    float rs = rsqrtf(1.f + EPS_);

    // phase 0: load raw x plane; build fused weights w80 and bias pieces
    for (int idx = tid; idx < PLANE; idx += 256) s_x[idx] = xp[idx];
    if (tid < 64) {
        float g = __ldg(&dbg[tid*V_ + v]) * rs;
        s_dbbg[tid] = __fdividef(__ldg(&dbb[tid*V_ + v]), g);
    }
    // w80 rows: 0-15 fq(=0.7071*g*Wq), 16-31 fk(=g*Wk), 32-47 fv(=g*Wv),
    //           48-63 pq(=0.7071*Wq), 64-79 pk(=Wk)
    for (int idx = tid; idx < 5120; idx += 256) {
        int j = idx >> 6, c = idx & 63;
        int orig; float s;
        if      (j < 16) { orig = j;      s = 0.70710678118f * __ldg(&dbg[c*V_ + v]) * rs; }
        else if (j < 32) { orig = j;      s = __ldg(&dbg[c*V_ + v]) * rs; }
        else if (j < 48) { orig = j + 16; s = __ldg(&dbg[c*V_ + v]) * rs; }
        else if (j < 64) { orig = j - 48; s = 0.70710678118f; }
        else             { orig = j - 48; s = 1.f; }
        s_w[idx] = __ldg(&qkvw[orig*64 + c]) * s;
    }
    if (tid < 48) {
        int orig = (tid < 32) ? tid : tid + 16;
        float s = (tid < 16) ? 0.70710678118f : 1.f;
        s_bias[tid] = __ldg(&qkvb[orig]) * s;
    }
    __syncthreads();

    // phase 0b: bias_j += sum_c w80[j][c] * dbbg[c]   (j < 48)
    if (tid < 48) {
        float b = s_bias[tid];
        const float* wr = s_w + tid*64;
        #pragma unroll 8
        for (int c = 0; c < 64; c++) b += wr[c] * s_dbbg[c];
        s_bias[tid] = b;
    }
    __syncthreads();

    // phase 1: 80-row GEMM on the single x plane; 16 tg x 16 rg, 5 rows per rg
    {
        int tg = tid & 15, rg = tid >> 4;
        int t0 = tg * 4;
        u64 acc[5][2];
        #pragma unroll
        for (int m = 0; m < 5; m++) { acc[m][0] = 0ULL; acc[m][1] = 0ULL; }
        #pragma unroll 4
        for (int c = 0; c < 64; c += 2) {
            u64 xa0 = *(const u64*)&s_x[c*64 + t0];
            u64 xa1 = *(const u64*)&s_x[c*64 + t0 + 2];
            u64 xb0 = *(const u64*)&s_x[(c+1)*64 + t0];
            u64 xb1 = *(const u64*)&s_x[(c+1)*64 + t0 + 2];
            #pragma unroll
            for (int m = 0; m < 5; m++) {
                u64 wp = *(const u64*)&s_w[(rg + 16*m)*64 + c];
                float2 wf = *(float2*)&wp;
                u64 w0 = dup2(wf.x), w1 = dup2(wf.y);
                acc[m][0] = ffma2(w0, xa0, acc[m][0]);
                acc[m][1] = ffma2(w0, xa1, acc[m][1]);
                acc[m][0] = ffma2(w1, xb0, acc[m][0]);
                acc[m][1] = ffma2(w1, xb1, acc[m][1]);
            }
        }
        const float* pePv = g_peP + (size_t)v*2048;
        #pragma unroll
        for (int m = 0; m < 5; m++) {
            float2 lo = *(float2*)&acc[m][0], hi = *(float2*)&acc[m][1];
            float4 o;
            if (m < 3) {
                float b = s_bias[rg + 16*m];
                o.x = lo.x + b; o.y = lo.y + b; o.z = hi.x + b; o.w = hi.y + b;
            } else {
                int pr = (m == 3) ? rg : rg + 16;
                float4 pp = *(const float4*)&pePv[pr*64 + t0];
                o.x = lo.x + pp.x; o.y = lo.y + pp.y; o.z = hi.x + pp.z; o.w = hi.y + pp.w;
            }
            float* dst = (m == 0) ? s_fq : (m == 1) ? s_fk : (m == 2) ? s_fv
                       : (m == 3) ? s_pq : s_pk;
            *(float4*)&dst[rg*64 + t0] = o;
        }
    }
    __syncthreads();

    // phase 2: mu_q = mean_t fq
    if (tid < 16) {
        float s = 0.f;
        #pragma unroll 8
        for (int t = 0; t < 64; t++) s += s_fq[tid*64 + t];
        s_mu[tid] = s * (1.f/64.f);
    }
    __syncthreads();

    // phase 3: attention core, t-pair f32x2 packed, tanh.approx
    {
        int s = tid & 63, hg = tid >> 6;
        #pragma unroll
        for (int hh = 0; hh < 2; hh++) {
            int h = hg + 4*hh;
            int r0 = 2*h, r1 = 2*h + 1;
            float mu0 = s_mu[r0], mu1 = s_mu[r1];
            u64 mu0d = dup2(mu0), mu1d = dup2(mu1);
            u64 fq0d = dup2(s_fq[r0*64 + s] - mu0);
            u64 fq1d = dup2(s_fq[r1*64 + s] - mu1);
            u64 pq0d = dup2(s_pq[r0*64 + s]);
            u64 pq1d = dup2(s_pq[r1*64 + s]);
            const u64* fk0p = (const u64*)&s_fk[r0*64];
            const u64* fk1p = (const u64*)&s_fk[r1*64];
            const u64* pk0p = (const u64*)&s_pk[r0*64];
            const u64* pk1p = (const u64*)&s_pk[r1*64];
            const u64* fv0p = (const u64*)&s_fv[r0*64];
            const u64* fv1p = (const u64*)&s_fv[r1*64];
            u64 a0 = 0ULL, a1 = 0ULL;
            #pragma unroll 4
            for (int tp = 0; tp < 32; tp++) {
                u64 fk0 = fk0p[tp], fk1 = fk1p[tp];
                u64 pk0 = pk0p[tp], pk1 = pk1p[tp];
                u64 lp = ffma2(pq1d, pk1, ffma2(pq0d, pk0, 0ULL));
                u64 pw = ffma2(fq1d, fk1, ffma2(fq0d, fk0, lp));
                u64 un = ffma2(mu1d, fk1, ffma2(mu0d, fk0, lp));
                float2 pwf = *(float2*)&pw, unf = *(float2*)&un;
                float w0 = tanha(pwf.x) + tanha(unf.x);
                float w1 = tanha(pwf.y) + tanha(unf.y);
                u64 w2 = pack2(w0, w1);
                a0 = ffma2(w2, fv0p[tp], a0);
                a1 = ffma2(w2, fv1p[tp], a1);
            }
            float2 A0 = *(float2*)&a0, A1 = *(float2*)&a1;
            s_ao[r0*64 + s] = A0.x + A0.y;
            s_ao[r1*64 + s] = A1.x + A1.y;
        }
    }
    __syncthreads();

    // phase 4: attn output projection (16x16) + residual + SE partials (ch 48..63)
    {
        int t = tid & 63, og = tid >> 6;
        const float* xres = g_xT + (size_t)(n*V_ + v)*PLANE + 48*64;
        float*       outp = g_sR + (size_t)(n*V_ + v)*PLANE + 48*64;
        int half = t >> 5;
        #pragma unroll
        for (int i = 0; i < 4; i++) {
            int o = og*4 + i;
            float acc = __ldg(&ab[o]);
            #pragma unroll
            for (int c = 0; c < 16; c++) acc += __ldg(&aw[o*16 + c]) * s_ao[c*64 + t];
            float res = acc + xres[o*64 + t];
            outp[o*64 + t] = res;
            float vsum = res;
            #pragma unroll
            for (int off = 16; off > 0; off >>= 1)
                vsum += __shfl_down_sync(0xffffffffu, vsum, off);
            if ((t & 31) == 0) s_scr[o*2 + half] = vsum;
        }
    }
    __syncthreads();
    if (tid < 16)
        g_part[(size_t)(n*V_ + v)*64 + 48 + tid] = s_scr[2*tid] + s_scr[2*tid+1];
}

// ---------------- K2: TCN branch, 4 planes per block ----------------
// 768 threads = 4 planes x (24 o-pairs x 8 t-groups). FFMA2-packed over o-pair.
// ALL 13 loads (4 LDS.128 x + 9 LDS.64 w) batched at top of each c-iteration:
// one latency exposure per c instead of ~10.
#define TCN_PL 4
#define TCN_THREADS (192*TCN_PL)
#define TCN_SMEM_BYTES ((size_t)(24*580*8 + TCN_PL*64*72*4))
__global__ __launch_bounds__(TCN_THREADS, 1)
void k_tcn(const float* __restrict__ tw, const float* __restrict__ tb,
           const float* __restrict__ tbg, const float* __restrict__ tbb) {
    extern __shared__ float smr[];
    float2* s_w2 = (float2*)smr;                 // 24*580 float2
    float*  s_xs = smr + 24*580*2;               // TCN_PL * 64*72 floats
    int tid = threadIdx.x;
    int plane0 = blockIdx.x * TCN_PL;

    for (int idx = tid; idx < 24*576; idx += TCN_THREADS) {
        int op = idx / 576, j = idx - op*576;
        float a = tw[(2*op  )*576 + j];
        float b = tw[(2*op+1)*576 + j];
        s_w2[op*580 + j] = make_float2(a, b);
    }
    for (int idx = tid; idx < TCN_PL*64*72; idx += TCN_THREADS) {
        int pl = idx / 4608, rem = idx - pl*4608;
        int c = rem / 72, j = rem - c*72;
        int t = j - 4;
        s_xs[idx] = (t >= 0 && t < T_)
                  ? g_xT[(size_t)(plane0 + pl)*PLANE + c*T_ + t] : 0.f;
    }
    __syncthreads();

    int pl = tid / 192, r = tid - pl*192;
    int op = r >> 3, tg = r & 7;
    int t0 = tg * 8;
    const float* xs = s_xs + pl*4608;

    u64 acc2[8];
    #pragma unroll
    for (int i = 0; i < 8; i++) acc2[i] = 0ULL;

    for (int c = 0; c < 64; c++) {
        // ---- all loads up front ----
        const float* xr = xs + c*72 + t0;
        float4 q0 = *(const float4*)(xr);
        float4 q1 = *(const float4*)(xr + 4);
        float4 q2 = *(const float4*)(xr + 8);
        float4 q3 = *(const float4*)(xr + 12);
        const u64* wp = (const u64*)(s_w2 + op*580 + c*9);
        u64 wr[9];
        #pragma unroll
        for (int k = 0; k < 9; k++) wr[k] = wp[k];
        // ---- expand x to packed pairs ----
        u64 xd[16];
        xd[0]=dup2(q0.x); xd[1]=dup2(q0.y); xd[2]=dup2(q0.z); xd[3]=dup2(q0.w);
        xd[4]=dup2(q1.x); xd[5]=dup2(q1.y); xd[6]=dup2(q1.z); xd[7]=dup2(q1.w);
        xd[8]=dup2(q2.x); xd[9]=dup2(q2.y); xd[10]=dup2(q2.z); xd[11]=dup2(q2.w);
        xd[12]=dup2(q3.x); xd[13]=dup2(q3.y); xd[14]=dup2(q3.z); xd[15]=dup2(q3.w);
        // ---- 72 FFMA2, no loads interleaved ----
        #pragma unroll
        for (int k = 0; k < 9; k++) {
            #pragma unroll
            for (int i = 0; i < 8; i++) acc2[i] = ffma2(wr[k], xd[i + k], acc2[i]);
        }
    }

    int o0 = 2*op, o1 = o0 + 1;
    float rsq = rsqrtf(1.f + EPS_);
    float ts0 = __ldg(&tbg[o0]) * rsq, ts1 = __ldg(&tbg[o1]) * rsq;
    float cb0 = __ldg(&tb[o0]) * ts0 + __ldg(&tbb[o0]);
    float cb1 = __ldg(&tb[o1]) * ts1 + __ldg(&tbb[o1]);
    float* out0 = g_sR + (size_t)(plane0 + pl)*PLANE + o0*T_;
    float* out1 = out0 + T_;
    float s0 = 0.f, s1 = 0.f;
    #pragma unroll
    for (int i = 0; i < 8; i++) {
        float2 p = *(float2*)&acc2[i];
        int t = t0 + i;
        float v0 = p.x*ts0 + cb0 + xs[o0*72 + 4 + t];
        float v1 = p.y*ts1 + cb1 + xs[o1*72 + 4 + t];
        out0[t] = v0; out1[t] = v1;
        s0 += v0; s1 += v1;
    }
    #pragma unroll
    for (int off = 4; off > 0; off >>= 1) {
        s0 += __shfl_down_sync(0xffffffffu, s0, off, 8);
        s1 += __shfl_down_sync(0xffffffffu, s1, off, 8);
    }
    if (tg == 0) {
        g_part[(size_t)(plane0 + pl)*64 + o0] = s0;
        g_part[(size_t)(plane0 + pl)*64 + o1] = s1;
    }
}

// ---------------- K3: SE gate MLP from partials, one block per n ----------------
__global__ void k_se(const float* __restrict__ f1w, const float* __restrict__ f1b,
                     const float* __restrict__ f2w, const float* __restrict__ f2b,
                     const float* __restrict__ bng) {
    __shared__ float s_red[4][64];
    __shared__ float s_se[64];
    __shared__ float s_h1[32];
    int n = blockIdx.x, tid = threadIdx.x;
    int c = tid & 63, vg = tid >> 6;
    float s = 0.f;
    for (int v = vg; v < V_; v += 4) s += g_part[(size_t)(n*V_ + v)*64 + c];
    s_red[vg][c] = s;
    __syncthreads();
    if (tid < 64) {
        s_se[tid] = (s_red[0][tid] + s_red[1][tid] + s_red[2][tid] + s_red[3][tid])
                    * (1.f/1600.f);
    }
    __syncthreads();
    if (tid < 32) {
        float a = f1b[tid];
        #pragma unroll
        for (int j = 0; j < 64; j++) a += f1w[tid*64 + j] * s_se[j];
        s_h1[tid] = fmaxf(a, 0.f);
    }
    __syncthreads();
    if (tid < 64) {
        float a = f2b[tid];
        #pragma unroll
        for (int j = 0; j < 32; j++) a += f2w[tid*32 + j] * s_h1[j];
        float sg = __fdividef(1.f, 1.f + __expf(-a));
        g_gmul[n*64 + tid] = (1.f + sg) * bng[tid] * rsqrtf(1.f + EPS_);
    }
}

// ---------------- K4: gate * BN * ReLU + transpose back to (N,C,T,V) ----------------
__global__ void k_final(const float* __restrict__ bnb, float* __restrict__ out) {
    __shared__ float s_buf[25*65];
    int b = blockIdx.x;
    int n = b >> 6, c = b & 63;
    const float* base = g_sR + (size_t)n*V_*PLANE + c*T_;
    for (int idx = threadIdx.x; idx < T_*V_; idx += 256) {
        int v = idx >> 6, t = idx & 63;
        s_buf[v*65 + t] = base[(size_t)v*PLANE + t];
    }
    __syncthreads();
    float m = g_gmul[n*64 + c], bb = bnb[c];
    float* op = out + (size_t)(n*64 + c)*(T_*V_);
    for (int idx = threadIdx.x; idx < T_*V_; idx += 256) {
        int t = idx / 25, v = idx - t*25;
        float val = s_buf[v*65 + t] * m + bb;
        op[idx] = fmaxf(val, 0.f);
    }
}

// ---------------- launcher ----------------
extern "C" void kernel_launch(void* const* d_in, const int* in_sizes, int n_in,
                              void* d_out, int out_size) {
    (void)in_sizes; (void)n_in; (void)out_size;
    const float* x    = (const float*)d_in[0];
    const float* pe   = (const float*)d_in[1];
    const float* dbg  = (const float*)d_in[2];
    const float* dbb  = (const float*)d_in[3];
    const float* qkvw = (const float*)d_in[4];
    const float* qkvb = (const float*)d_in[5];
    const float* aw   = (const float*)d_in[6];
    const float* ab   = (const float*)d_in[7];
    const float* tw   = (const float*)d_in[8];
    const float* tb   = (const float*)d_in[9];
    const float* tbg  = (const float*)d_in[10];
    const float* tbb  = (const float*)d_in[11];
    const float* f1w  = (const float*)d_in[12];
    const float* f1b  = (const float*)d_in[13];
    const float* f2w  = (const float*)d_in[14];
    const float* f2b  = (const float*)d_in[15];
    const float* bng  = (const float*)d_in[16];
    const float* bnb  = (const float*)d_in[17];

    cudaFuncSetAttribute(k_attn, cudaFuncAttributeMaxDynamicSharedMemorySize, (int)ATTN_SMEM_BYTES);
    cudaFuncSetAttribute(k_tcn,  cudaFuncAttributeMaxDynamicSharedMemorySize, (int)TCN_SMEM_BYTES);

    // launch order kept identical so ncu recaptures k_tcn
    k_transpose<<<N_B*C_, 256>>>(x);
    k_peproj<<<V_, 256>>>(pe, qkvw, qkvb);
    k_attn<<<NV, 256, ATTN_SMEM_BYTES>>>(dbg, dbb, qkvw, qkvb, aw, ab);
    k_tcn <<<NV/TCN_PL, TCN_THREADS, TCN_SMEM_BYTES>>>(tw, tb, tbg, tbb);
    k_se  <<<N_B, 256>>>(f1w, f1b, f2w, f2b, bng);
    k_final<<<N_B*C_, 256>>>(bnb, (float*)d_out);
}

// round 15
// speedup vs baseline: 1.6227x; 1.1130x over previous
#include <cuda_runtime.h>
#include <math.h>

// ---------------- problem constants ----------------
#define N_B   64
#define C_    64
#define T_    64
#define V_    25
#define NV    (N_B*V_)       // 1600 sequences
#define PLANE (C_*T_)        // 4096 floats per (n,v) plane
#define EPS_  1e-5f

typedef unsigned long long u64;

// ---------------- device scratch (no allocations allowed) ----------------
__device__ float g_xT [(size_t)NV*PLANE];   // x transposed: [n][v][c][t]
__device__ float g_sR [(size_t)NV*PLANE];   // result (branches + residual): [n][v][c][t]
__device__ float g_peP[(size_t)V_*32*64];   // pe projection: [v][r(32)][t]
__device__ float g_part[(size_t)NV*C_];     // per-(n,v,c) sums over t (for SE)
__device__ float g_gmul[N_B*C_];            // per-(n,ch) (1+gate)*bn_scale

// ---------------- helpers ----------------
__device__ __forceinline__ u64 ffma2(u64 a, u64 b, u64 c) {
    u64 d;
    asm("fma.rn.f32x2 %0, %1, %2, %3;" : "=l"(d) : "l"(a), "l"(b), "l"(c));
    return d;
}
__device__ __forceinline__ u64 dup2(float a) {
    u64 r;
    asm("mov.b64 %0, {%1, %1};" : "=l"(r) : "f"(a));
    return r;
}
__device__ __forceinline__ u64 pack2(float lo, float hi) {
    u64 r;
    asm("mov.b64 %0, {%1, %2};" : "=l"(r) : "f"(lo), "f"(hi));
    return r;
}
__device__ __forceinline__ float tanha(float x) {
    float y;
    asm("tanh.approx.f32 %0, %1;" : "=f"(y) : "f"(x));
    return y;
}

// ---------------- K0: transpose x into [n][v][c][t] planes ----------------
__global__ void k_transpose(const float* __restrict__ x) {
    __shared__ float buf[T_*V_];
    int b = blockIdx.x;
    const float* src = x + (size_t)b*(T_*V_);
    for (int i = threadIdx.x; i < T_*V_; i += blockDim.x) buf[i] = src[i];
    __syncthreads();
    int n = b >> 6, c = b & 63;
    for (int i = threadIdx.x; i < T_*V_; i += blockDim.x) {
        int v = i >> 6, t = i & 63;
        g_xT[((size_t)(n*V_ + v))*PLANE + c*T_ + t] = buf[t*V_ + v];
    }
}

// ---------------- K0b: pe projection (per v) ----------------
__global__ void k_peproj(const float* __restrict__ pe, const float* __restrict__ qkvw,
                         const float* __restrict__ qkvb) {
    __shared__ float s_pe[64*64];    // [c][t]
    int v = blockIdx.x, tid = threadIdx.x;
    for (int i = tid; i < 4096; i += 256) {
        int c = i >> 6, t = i & 63;
        s_pe[i] = pe[(size_t)(c*64 + t)*V_ + v];
    }
    __syncthreads();
    int r = tid >> 3;            // 0..31
    int t0 = (tid & 7) * 8;      // 8 t's
    float s = (r < 16) ? 0.70710678118f : 1.f;
    float acc[8];
    #pragma unroll
    for (int i = 0; i < 8; i++) acc[i] = __ldg(&qkvb[r]);
    for (int c = 0; c < 64; c++) {
        float w = __ldg(&qkvw[r*64 + c]);
        #pragma unroll
        for (int i = 0; i < 8; i++) acc[i] += w * s_pe[c*64 + t0 + i];
    }
    float* dst = g_peP + (size_t)v*2048 + r*64 + t0;
    #pragma unroll
    for (int i = 0; i < 8; i++) dst[i] = acc[i] * s;
}

// ---------------- K1: fused attention branch, one block per (n,v) ----------------
#define ATTN_SMEM_BYTES ((size_t)15552*4)
__global__ __launch_bounds__(256, 3)
void k_attn(const float* __restrict__ dbg, const float* __restrict__ dbb,
            const float* __restrict__ qkvw, const float* __restrict__ qkvb,
            const float* __restrict__ aw,  const float* __restrict__ ab) {
    extern __shared__ float sm[];
    float* s_x   = sm;
    float* s_w   = sm + 4096;
    float* s_fq  = sm + 9216;
    float* s_fk  = sm + 10240;
    float* s_fv  = sm + 11264;
    float* s_pq  = sm + 12288;
    float* s_pk  = sm + 13312;
    float* s_ao  = sm + 14336;
    float* s_dbbg= sm + 15360;
    float* s_bias= sm + 15424;
    float* s_mu  = sm + 15504;
    float* s_scr = sm + 15520;

    int tid = threadIdx.x;
    int n = blockIdx.x / V_, v = blockIdx.x % V_;
    const float* xp = g_xT + (size_t)(n*V_ + v)*PLANE;
    float rs = rsqrtf(1.f + EPS_);

    for (int idx = tid; idx < PLANE; idx += 256) s_x[idx] = xp[idx];
    if (tid < 64) {
        float g = __ldg(&dbg[tid*V_ + v]) * rs;
        s_dbbg[tid] = __fdividef(__ldg(&dbb[tid*V_ + v]), g);
    }
    for (int idx = tid; idx < 5120; idx += 256) {
        int j = idx >> 6, c = idx & 63;
        int orig; float s;
        if      (j < 16) { orig = j;      s = 0.70710678118f * __ldg(&dbg[c*V_ + v]) * rs; }
        else if (j < 32) { orig = j;      s = __ldg(&dbg[c*V_ + v]) * rs; }
        else if (j < 48) { orig = j + 16; s = __ldg(&dbg[c*V_ + v]) * rs; }
        else if (j < 64) { orig = j - 48; s = 0.70710678118f; }
        else             { orig = j - 48; s = 1.f; }
        s_w[idx] = __ldg(&qkvw[orig*64 + c]) * s;
    }
    if (tid < 48) {
        int orig = (tid < 32) ? tid : tid + 16;
        float s = (tid < 16) ? 0.70710678118f : 1.f;
        s_bias[tid] = __ldg(&qkvb[orig]) * s;
    }
    __syncthreads();

    if (tid < 48) {
        float b = s_bias[tid];
        const float* wr = s_w + tid*64;
        #pragma unroll 8
        for (int c = 0; c < 64; c++) b += wr[c] * s_dbbg[c];
        s_bias[tid] = b;
    }
    __syncthreads();

    {
        int tg = tid & 15, rg = tid >> 4;
        int t0 = tg * 4;
        u64 acc[5][2];
        #pragma unroll
        for (int m = 0; m < 5; m++) { acc[m][0] = 0ULL; acc[m][1] = 0ULL; }
        #pragma unroll 4
        for (int c = 0; c < 64; c += 2) {
            u64 xa0 = *(const u64*)&s_x[c*64 + t0];
            u64 xa1 = *(const u64*)&s_x[c*64 + t0 + 2];
            u64 xb0 = *(const u64*)&s_x[(c+1)*64 + t0];
            u64 xb1 = *(const u64*)&s_x[(c+1)*64 + t0 + 2];
            #pragma unroll
            for (int m = 0; m < 5; m++) {
                u64 wp = *(const u64*)&s_w[(rg + 16*m)*64 + c];
                float2 wf = *(float2*)&wp;
                u64 w0 = dup2(wf.x), w1 = dup2(wf.y);
                acc[m][0] = ffma2(w0, xa0, acc[m][0]);
                acc[m][1] = ffma2(w0, xa1, acc[m][1]);
                acc[m][0] = ffma2(w1, xb0, acc[m][0]);
                acc[m][1] = ffma2(w1, xb1, acc[m][1]);
            }
        }
        const float* pePv = g_peP + (size_t)v*2048;
        #pragma unroll
        for (int m = 0; m < 5; m++) {
            float2 lo = *(float2*)&acc[m][0], hi = *(float2*)&acc[m][1];
            float4 o;
            if (m < 3) {
                float b = s_bias[rg + 16*m];
                o.x = lo.x + b; o.y = lo.y + b; o.z = hi.x + b; o.w = hi.y + b;
            } else {
                int pr = (m == 3) ? rg : rg + 16;
                float4 pp = *(const float4*)&pePv[pr*64 + t0];
                o.x = lo.x + pp.x; o.y = lo.y + pp.y; o.z = hi.x + pp.z; o.w = hi.y + pp.w;
            }
            float* dst = (m == 0) ? s_fq : (m == 1) ? s_fk : (m == 2) ? s_fv
                       : (m == 3) ? s_pq : s_pk;
            *(float4*)&dst[rg*64 + t0] = o;
        }
    }
    __syncthreads();

    if (tid < 16) {
        float s = 0.f;
        #pragma unroll 8
        for (int t = 0; t < 64; t++) s += s_fq[tid*64 + t];
        s_mu[tid] = s * (1.f/64.f);
    }
    __syncthreads();

    {
        int s = tid & 63, hg = tid >> 6;
        #pragma unroll
        for (int hh = 0; hh < 2; hh++) {
            int h = hg + 4*hh;
            int r0 = 2*h, r1 = 2*h + 1;
            float mu0 = s_mu[r0], mu1 = s_mu[r1];
            u64 mu0d = dup2(mu0), mu1d = dup2(mu1);
            u64 fq0d = dup2(s_fq[r0*64 + s] - mu0);
            u64 fq1d = dup2(s_fq[r1*64 + s] - mu1);
            u64 pq0d = dup2(s_pq[r0*64 + s]);
            u64 pq1d = dup2(s_pq[r1*64 + s]);
            const u64* fk0p = (const u64*)&s_fk[r0*64];
            const u64* fk1p = (const u64*)&s_fk[r1*64];
            const u64* pk0p = (const u64*)&s_pk[r0*64];
            const u64* pk1p = (const u64*)&s_pk[r1*64];
            const u64* fv0p = (const u64*)&s_fv[r0*64];
            const u64* fv1p = (const u64*)&s_fv[r1*64];
            u64 a0 = 0ULL, a1 = 0ULL;
            #pragma unroll 4
            for (int tp = 0; tp < 32; tp++) {
                u64 fk0 = fk0p[tp], fk1 = fk1p[tp];
                u64 pk0 = pk0p[tp], pk1 = pk1p[tp];
                u64 lp = ffma2(pq1d, pk1, ffma2(pq0d, pk0, 0ULL));
                u64 pw = ffma2(fq1d, fk1, ffma2(fq0d, fk0, lp));
                u64 un = ffma2(mu1d, fk1, ffma2(mu0d, fk0, lp));
                float2 pwf = *(float2*)&pw, unf = *(float2*)&un;
                float w0 = tanha(pwf.x) + tanha(unf.x);
                float w1 = tanha(pwf.y) + tanha(unf.y);
                u64 w2 = pack2(w0, w1);
                a0 = ffma2(w2, fv0p[tp], a0);
                a1 = ffma2(w2, fv1p[tp], a1);
            }
            float2 A0 = *(float2*)&a0, A1 = *(float2*)&a1;
            s_ao[r0*64 + s] = A0.x + A0.y;
            s_ao[r1*64 + s] = A1.x + A1.y;
        }
    }
    __syncthreads();

    {
        int t = tid & 63, og = tid >> 6;
        const float* xres = g_xT + (size_t)(n*V_ + v)*PLANE + 48*64;
        float*       outp = g_sR + (size_t)(n*V_ + v)*PLANE + 48*64;
        int half = t >> 5;
        #pragma unroll
        for (int i = 0; i < 4; i++) {
            int o = og*4 + i;
            float acc = __ldg(&ab[o]);
            #pragma unroll
            for (int c = 0; c < 16; c++) acc += __ldg(&aw[o*16 + c]) * s_ao[c*64 + t];
            float res = acc + xres[o*64 + t];
            outp[o*64 + t] = res;
            float vsum = res;
            #pragma unroll
            for (int off = 16; off > 0; off >>= 1)
                vsum += __shfl_down_sync(0xffffffffu, vsum, off);
            if ((t & 31) == 0) s_scr[o*2 + half] = vsum;
        }
    }
    __syncthreads();
    if (tid < 16)
        g_part[(size_t)(n*V_ + v)*64 + 48 + tid] = s_scr[2*tid] + s_scr[2*tid+1];
}

// ---------------- K2: TCN branch, 4 planes per block (R11 winner) ----------------
#define TCN_PL 4
#define TCN_THREADS (192*TCN_PL)
#define TCN_SMEM_BYTES ((size_t)(24*580*8 + TCN_PL*64*72*4))
__global__ __launch_bounds__(TCN_THREADS, 1)
void k_tcn(const float* __restrict__ tw, const float* __restrict__ tb,
           const float* __restrict__ tbg, const float* __restrict__ tbb) {
    extern __shared__ float smr[];
    float2* s_w2 = (float2*)smr;                 // 24*580 float2
    float*  s_xs = smr + 24*580*2;               // TCN_PL * 64*72 floats
    int tid = threadIdx.x;
    int plane0 = blockIdx.x * TCN_PL;

    for (int idx = tid; idx < 24*576; idx += TCN_THREADS) {
        int op = idx / 576, j = idx - op*576;
        float a = tw[(2*op  )*576 + j];
        float b = tw[(2*op+1)*576 + j];
        s_w2[op*580 + j] = make_float2(a, b);
    }
    for (int idx = tid; idx < TCN_PL*64*72; idx += TCN_THREADS) {
        int pl = idx / 4608, rem = idx - pl*4608;
        int c = rem / 72, j = rem - c*72;
        int t = j - 4;
        s_xs[idx] = (t >= 0 && t < T_)
                  ? g_xT[(size_t)(plane0 + pl)*PLANE + c*T_ + t] : 0.f;
    }
    __syncthreads();

    int pl = tid / 192, r = tid - pl*192;
    int op = r >> 3, tg = r & 7;
    int t0 = tg * 8;
    const float* xs = s_xs + pl*4608;

    u64 acc2[8];
    #pragma unroll
    for (int i = 0; i < 8; i++) acc2[i] = 0ULL;

    for (int c = 0; c < 64; c++) {
        const float* xr = xs + c*72 + t0;
        float4 q0 = *(const float4*)(xr);
        float4 q1 = *(const float4*)(xr + 4);
        float4 q2 = *(const float4*)(xr + 8);
        float4 q3 = *(const float4*)(xr + 12);
        const u64* wp = (const u64*)(s_w2 + op*580 + c*9);
        u64 wr[9];
        #pragma unroll
        for (int k = 0; k < 9; k++) wr[k] = wp[k];
        u64 xd[16];
        xd[0]=dup2(q0.x); xd[1]=dup2(q0.y); xd[2]=dup2(q0.z); xd[3]=dup2(q0.w);
        xd[4]=dup2(q1.x); xd[5]=dup2(q1.y); xd[6]=dup2(q1.z); xd[7]=dup2(q1.w);
        xd[8]=dup2(q2.x); xd[9]=dup2(q2.y); xd[10]=dup2(q2.z); xd[11]=dup2(q2.w);
        xd[12]=dup2(q3.x); xd[13]=dup2(q3.y); xd[14]=dup2(q3.z); xd[15]=dup2(q3.w);
        #pragma unroll
        for (int k = 0; k < 9; k++) {
            #pragma unroll
            for (int i = 0; i < 8; i++) acc2[i] = ffma2(wr[k], xd[i + k], acc2[i]);
        }
    }

    int o0 = 2*op, o1 = o0 + 1;
    float rsq = rsqrtf(1.f + EPS_);
    float ts0 = __ldg(&tbg[o0]) * rsq, ts1 = __ldg(&tbg[o1]) * rsq;
    float cb0 = __ldg(&tb[o0]) * ts0 + __ldg(&tbb[o0]);
    float cb1 = __ldg(&tb[o1]) * ts1 + __ldg(&tbb[o1]);
    float* out0 = g_sR + (size_t)(plane0 + pl)*PLANE + o0*T_;
    float* out1 = out0 + T_;
    float s0 = 0.f, s1 = 0.f;
    #pragma unroll
    for (int i = 0; i < 8; i++) {
        float2 p = *(float2*)&acc2[i];
        int t = t0 + i;
        float v0 = p.x*ts0 + cb0 + xs[o0*72 + 4 + t];
        float v1 = p.y*ts1 + cb1 + xs[o1*72 + 4 + t];
        out0[t] = v0; out1[t] = v1;
        s0 += v0; s1 += v1;
    }
    #pragma unroll
    for (int off = 4; off > 0; off >>= 1) {
        s0 += __shfl_down_sync(0xffffffffu, s0, off, 8);
        s1 += __shfl_down_sync(0xffffffffu, s1, off, 8);
    }
    if (tg == 0) {
        g_part[(size_t)(plane0 + pl)*64 + o0] = s0;
        g_part[(size_t)(plane0 + pl)*64 + o1] = s1;
    }
}

// ---------------- K3: SE gate MLP from partials, one block per n ----------------
__global__ void k_se(const float* __restrict__ f1w, const float* __restrict__ f1b,
                     const float* __restrict__ f2w, const float* __restrict__ f2b,
                     const float* __restrict__ bng) {
    __shared__ float s_red[4][64];
    __shared__ float s_se[64];
    __shared__ float s_h1[32];
    int n = blockIdx.x, tid = threadIdx.x;
    int c = tid & 63, vg = tid >> 6;
    float s = 0.f;
    for (int v = vg; v < V_; v += 4) s += g_part[(size_t)(n*V_ + v)*64 + c];
    s_red[vg][c] = s;
    __syncthreads();
    if (tid < 64) {
        s_se[tid] = (s_red[0][tid] + s_red[1][tid] + s_red[2][tid] + s_red[3][tid])
                    * (1.f/1600.f);
    }
    __syncthreads();
    if (tid < 32) {
        float a = f1b[tid];
        #pragma unroll
        for (int j = 0; j < 64; j++) a += f1w[tid*64 + j] * s_se[j];
        s_h1[tid] = fmaxf(a, 0.f);
    }
    __syncthreads();
    if (tid < 64) {
        float a = f2b[tid];
        #pragma unroll
        for (int j = 0; j < 32; j++) a += f2w[tid*32 + j] * s_h1[j];
        float sg = __fdividef(1.f, 1.f + __expf(-a));
        g_gmul[n*64 + tid] = (1.f + sg) * bng[tid] * rsqrtf(1.f + EPS_);
    }
}

// ---------------- K4: gate * BN * ReLU + transpose back to (N,C,T,V) ----------------
__global__ void k_final(const float* __restrict__ bnb, float* __restrict__ out) {
    __shared__ float s_buf[25*65];
    int b = blockIdx.x;
    int n = b >> 6, c = b & 63;
    const float* base = g_sR + (size_t)n*V_*PLANE + c*T_;
    for (int idx = threadIdx.x; idx < T_*V_; idx += 256) {
        int v = idx >> 6, t = idx & 63;
        s_buf[v*65 + t] = base[(size_t)v*PLANE + t];
    }
    __syncthreads();
    float m = g_gmul[n*64 + c], bb = bnb[c];
    float* op = out + (size_t)(n*64 + c)*(T_*V_);
    for (int idx = threadIdx.x; idx < T_*V_; idx += 256) {
        int t = idx / 25, v = idx - t*25;
        float val = s_buf[v*65 + t] * m + bb;
        op[idx] = fmaxf(val, 0.f);
    }
}

// ---------------- launcher: fork tcn onto a side stream, overlap with attn ----------------
extern "C" void kernel_launch(void* const* d_in, const int* in_sizes, int n_in,
                              void* d_out, int out_size) {
    (void)in_sizes; (void)n_in; (void)out_size;
    const float* x    = (const float*)d_in[0];
    const float* pe   = (const float*)d_in[1];
    const float* dbg  = (const float*)d_in[2];
    const float* dbb  = (const float*)d_in[3];
    const float* qkvw = (const float*)d_in[4];
    const float* qkvb = (const float*)d_in[5];
    const float* aw   = (const float*)d_in[6];
    const float* ab   = (const float*)d_in[7];
    const float* tw   = (const float*)d_in[8];
    const float* tb   = (const float*)d_in[9];
    const float* tbg  = (const float*)d_in[10];
    const float* tbb  = (const float*)d_in[11];
    const float* f1w  = (const float*)d_in[12];
    const float* f1b  = (const float*)d_in[13];
    const float* f2w  = (const float*)d_in[14];
    const float* f2b  = (const float*)d_in[15];
    const float* bng  = (const float*)d_in[16];
    const float* bnb  = (const float*)d_in[17];

    cudaFuncSetAttribute(k_attn, cudaFuncAttributeMaxDynamicSharedMemorySize, (int)ATTN_SMEM_BYTES);
    cudaFuncSetAttribute(k_tcn,  cudaFuncAttributeMaxDynamicSharedMemorySize, (int)TCN_SMEM_BYTES);

    // side stream + fork/join events (host-side objects; no device allocation).
    // Created fresh each call; intentionally not destroyed (streams/events that
    // participate in an active capture must outlive it).
    cudaStream_t s2;
    cudaStreamCreateWithFlags(&s2, cudaStreamNonBlocking);
    cudaEvent_t e1, e2;
    cudaEventCreateWithFlags(&e1, cudaEventDisableTiming);
    cudaEventCreateWithFlags(&e2, cudaEventDisableTiming);

    // main stream: transpose -> (fork) -> peproj -> attn -> (join) -> se -> final
    // side stream:             tcn
    k_transpose<<<N_B*C_, 256>>>(x);
    cudaEventRecord(e1, 0);
    cudaStreamWaitEvent(s2, e1, 0);
    k_tcn<<<NV/TCN_PL, TCN_THREADS, TCN_SMEM_BYTES, s2>>>(tw, tb, tbg, tbb);
    k_peproj<<<V_, 256>>>(pe, qkvw, qkvb);
    k_attn<<<NV, 256, ATTN_SMEM_BYTES>>>(dbg, dbb, qkvw, qkvb, aw, ab);
    cudaEventRecord(e2, s2);
    cudaStreamWaitEvent(0, e2, 0);
    k_se<<<N_B, 256>>>(f1w, f1b, f2w, f2b, bng);
    k_final<<<N_B*C_, 256>>>(bnb, (float*)d_out);
}

// round 17
// speedup vs baseline: 2.1167x; 1.3045x over previous
#include <cuda_runtime.h>
#include <math.h>
#include <stdint.h>

// ---------------- problem constants ----------------
#define N_B   64
#define C_    64
#define T_    64
#define V_    25
#define NV    (N_B*V_)       // 1600 sequences
#define PLANE (C_*T_)        // 4096 floats per (n,v) plane
#define EPS_  1e-5f

typedef unsigned long long u64;

// ---------------- device scratch (no allocations allowed) ----------------
__device__ float g_xT [(size_t)NV*PLANE];   // x transposed: [n][v][c][t]
__device__ float g_sR [(size_t)NV*PLANE];   // result (branches + residual): [n][v][c][t]
__device__ float g_peP[(size_t)V_*32*64];   // pe projection: [v][r(32)][t]
__device__ float g_wTm[48*576];             // tcn weights tf32 bits: [o][k*64+c]
__device__ float g_part[(size_t)NV*C_];     // per-(n,v,c) sums over t (for SE)
__device__ float g_gmul[N_B*C_];            // per-(n,ch) (1+gate)*bn_scale

// ---------------- helpers ----------------
__device__ __forceinline__ u64 ffma2(u64 a, u64 b, u64 c) {
    u64 d;
    asm("fma.rn.f32x2 %0, %1, %2, %3;" : "=l"(d) : "l"(a), "l"(b), "l"(c));
    return d;
}
__device__ __forceinline__ u64 dup2(float a) {
    u64 r;
    asm("mov.b64 %0, {%1, %1};" : "=l"(r) : "f"(a));
    return r;
}
__device__ __forceinline__ u64 pack2(float lo, float hi) {
    u64 r;
    asm("mov.b64 %0, {%1, %2};" : "=l"(r) : "f"(lo), "f"(hi));
    return r;
}
__device__ __forceinline__ float tanha(float x) {
    float y;
    asm("tanh.approx.f32 %0, %1;" : "=f"(y) : "f"(x));
    return y;
}
__device__ __forceinline__ void mma8(float* d, uint32_t a0, uint32_t a1,
                                     uint32_t a2, uint32_t a3,
                                     uint32_t b0, uint32_t b1) {
    asm("mma.sync.aligned.m16n8k8.row.col.f32.tf32.tf32.f32 "
        "{%0,%1,%2,%3},{%4,%5,%6,%7},{%8,%9},{%0,%1,%2,%3};"
        : "+f"(d[0]), "+f"(d[1]), "+f"(d[2]), "+f"(d[3])
        : "r"(a0), "r"(a1), "r"(a2), "r"(a3), "r"(b0), "r"(b1));
}

// ---------------- K0: transpose x into [n][v][c][t] planes + W prep ----------------
__global__ void k_transpose(const float* __restrict__ x, const float* __restrict__ tw) {
    __shared__ float buf[T_*V_];
    int b = blockIdx.x;
    if (b < N_B*C_) {
        const float* src = x + (size_t)b*(T_*V_);
        for (int i = threadIdx.x; i < T_*V_; i += blockDim.x) buf[i] = src[i];
        __syncthreads();
        int n = b >> 6, c = b & 63;
        for (int i = threadIdx.x; i < T_*V_; i += blockDim.x) {
            int v = i >> 6, t = i & 63;
            g_xT[((size_t)(n*V_ + v))*PLANE + c*T_ + t] = buf[t*V_ + v];
        }
    } else {
        int o = b - N_B*C_;    // 0..47: tw[o][c][k] -> g_wTm[o][k*64+c], tf32-rounded
        for (int i = threadIdx.x; i < 576; i += blockDim.x) {
            int c = i / 9, k = i - c*9;
            uint32_t tf;
            asm("cvt.rna.tf32.f32 %0, %1;" : "=r"(tf) : "f"(tw[o*576 + i]));
            g_wTm[o*576 + k*64 + c] = __uint_as_float(tf);
        }
    }
}

// ---------------- K0b: pe projection (per v) ----------------
__global__ void k_peproj(const float* __restrict__ pe, const float* __restrict__ qkvw,
                         const float* __restrict__ qkvb) {
    __shared__ float s_pe[64*64];    // [c][t]
    int v = blockIdx.x, tid = threadIdx.x;
    for (int i = tid; i < 4096; i += 256) {
        int c = i >> 6, t = i & 63;
        s_pe[i] = pe[(size_t)(c*64 + t)*V_ + v];
    }
    __syncthreads();
    int r = tid >> 3;
    int t0 = (tid & 7) * 8;
    float s = (r < 16) ? 0.70710678118f : 1.f;
    float acc[8];
    #pragma unroll
    for (int i = 0; i < 8; i++) acc[i] = __ldg(&qkvb[r]);
    for (int c = 0; c < 64; c++) {
        float w = __ldg(&qkvw[r*64 + c]);
        #pragma unroll
        for (int i = 0; i < 8; i++) acc[i] += w * s_pe[c*64 + t0 + i];
    }
    float* dst = g_peP + (size_t)v*2048 + r*64 + t0;
    #pragma unroll
    for (int i = 0; i < 8; i++) dst[i] = acc[i] * s;
}

// ---------------- K1: fused attention branch (unchanged R15 winner) ----------------
#define ATTN_SMEM_BYTES ((size_t)15552*4)
__global__ __launch_bounds__(256, 3)
void k_attn(const float* __restrict__ dbg, const float* __restrict__ dbb,
            const float* __restrict__ qkvw, const float* __restrict__ qkvb,
            const float* __restrict__ aw,  const float* __restrict__ ab) {
    extern __shared__ float sm[];
    float* s_x   = sm;
    float* s_w   = sm + 4096;
    float* s_fq  = sm + 9216;
    float* s_fk  = sm + 10240;
    float* s_fv  = sm + 11264;
    float* s_pq  = sm + 12288;
    float* s_pk  = sm + 13312;
    float* s_ao  = sm + 14336;
    float* s_dbbg= sm + 15360;
    float* s_bias= sm + 15424;
    float* s_mu  = sm + 15504;
    float* s_scr = sm + 15520;

    int tid = threadIdx.x;
    int n = blockIdx.x / V_, v = blockIdx.x % V_;
    const float* xp = g_xT + (size_t)(n*V_ + v)*PLANE;
    float rs = rsqrtf(1.f + EPS_);

    for (int idx = tid; idx < PLANE; idx += 256) s_x[idx] = xp[idx];
    if (tid < 64) {
        float g = __ldg(&dbg[tid*V_ + v]) * rs;
        s_dbbg[tid] = __fdividef(__ldg(&dbb[tid*V_ + v]), g);
    }
    for (int idx = tid; idx < 5120; idx += 256) {
        int j = idx >> 6, c = idx & 63;
        int orig; float s;
        if      (j < 16) { orig = j;      s = 0.70710678118f * __ldg(&dbg[c*V_ + v]) * rs; }
        else if (j < 32) { orig = j;      s = __ldg(&dbg[c*V_ + v]) * rs; }
        else if (j < 48) { orig = j + 16; s = __ldg(&dbg[c*V_ + v]) * rs; }
        else if (j < 64) { orig = j - 48; s = 0.70710678118f; }
        else             { orig = j - 48; s = 1.f; }
        s_w[idx] = __ldg(&qkvw[orig*64 + c]) * s;
    }
    if (tid < 48) {
        int orig = (tid < 32) ? tid : tid + 16;
        float s = (tid < 16) ? 0.70710678118f : 1.f;
        s_bias[tid] = __ldg(&qkvb[orig]) * s;
    }
    __syncthreads();

    if (tid < 48) {
        float b = s_bias[tid];
        const float* wr = s_w + tid*64;
        #pragma unroll 8
        for (int c = 0; c < 64; c++) b += wr[c] * s_dbbg[c];
        s_bias[tid] = b;
    }
    __syncthreads();

    {
        int tg = tid & 15, rg = tid >> 4;
        int t0 = tg * 4;
        u64 acc[5][2];
        #pragma unroll
        for (int m = 0; m < 5; m++) { acc[m][0] = 0ULL; acc[m][1] = 0ULL; }
        #pragma unroll 4
        for (int c = 0; c < 64; c += 2) {
            u64 xa0 = *(const u64*)&s_x[c*64 + t0];
            u64 xa1 = *(const u64*)&s_x[c*64 + t0 + 2];
            u64 xb0 = *(const u64*)&s_x[(c+1)*64 + t0];
            u64 xb1 = *(const u64*)&s_x[(c+1)*64 + t0 + 2];
            #pragma unroll
            for (int m = 0; m < 5; m++) {
                u64 wp = *(const u64*)&s_w[(rg + 16*m)*64 + c];
                float2 wf = *(float2*)&wp;
                u64 w0 = dup2(wf.x), w1 = dup2(wf.y);
                acc[m][0] = ffma2(w0, xa0, acc[m][0]);
                acc[m][1] = ffma2(w0, xa1, acc[m][1]);
                acc[m][0] = ffma2(w1, xb0, acc[m][0]);
                acc[m][1] = ffma2(w1, xb1, acc[m][1]);
            }
        }
        const float* pePv = g_peP + (size_t)v*2048;
        #pragma unroll
        for (int m = 0; m < 5; m++) {
            float2 lo = *(float2*)&acc[m][0], hi = *(float2*)&acc[m][1];
            float4 o;
            if (m < 3) {
                float b = s_bias[rg + 16*m];
                o.x = lo.x + b; o.y = lo.y + b; o.z = hi.x + b; o.w = hi.y + b;
            } else {
                int pr = (m == 3) ? rg : rg + 16;
                float4 pp = *(const float4*)&pePv[pr*64 + t0];
                o.x = lo.x + pp.x; o.y = lo.y + pp.y; o.z = hi.x + pp.z; o.w = hi.y + pp.w;
            }
            float* dst = (m == 0) ? s_fq : (m == 1) ? s_fk : (m == 2) ? s_fv
                       : (m == 3) ? s_pq : s_pk;
            *(float4*)&dst[rg*64 + t0] = o;
        }
    }
    __syncthreads();

    if (tid < 16) {
        float s = 0.f;
        #pragma unroll 8
        for (int t = 0; t < 64; t++) s += s_fq[tid*64 + t];
        s_mu[tid] = s * (1.f/64.f);
    }
    __syncthreads();

    {
        int s = tid & 63, hg = tid >> 6;
        #pragma unroll
        for (int hh = 0; hh < 2; hh++) {
            int h = hg + 4*hh;
            int r0 = 2*h, r1 = 2*h + 1;
            float mu0 = s_mu[r0], mu1 = s_mu[r1];
            u64 mu0d = dup2(mu0), mu1d = dup2(mu1);
            u64 fq0d = dup2(s_fq[r0*64 + s] - mu0);
            u64 fq1d = dup2(s_fq[r1*64 + s] - mu1);
            u64 pq0d = dup2(s_pq[r0*64 + s]);
            u64 pq1d = dup2(s_pq[r1*64 + s]);
            const u64* fk0p = (const u64*)&s_fk[r0*64];
            const u64* fk1p = (const u64*)&s_fk[r1*64];
            const u64* pk0p = (const u64*)&s_pk[r0*64];
            const u64* pk1p = (const u64*)&s_pk[r1*64];
            const u64* fv0p = (const u64*)&s_fv[r0*64];
            const u64* fv1p = (const u64*)&s_fv[r1*64];
            u64 a0 = 0ULL, a1 = 0ULL;
            #pragma unroll 4
            for (int tp = 0; tp < 32; tp++) {
                u64 fk0 = fk0p[tp], fk1 = fk1p[tp];
                u64 pk0 = pk0p[tp], pk1 = pk1p[tp];
                u64 lp = ffma2(pq1d, pk1, ffma2(pq0d, pk0, 0ULL));
                u64 pw = ffma2(fq1d, fk1, ffma2(fq0d, fk0, lp));
                u64 un = ffma2(mu1d, fk1, ffma2(mu0d, fk0, lp));
                float2 pwf = *(float2*)&pw, unf = *(float2*)&un;
                float w0 = tanha(pwf.x) + tanha(unf.x);
                float w1 = tanha(pwf.y) + tanha(unf.y);
                u64 w2 = pack2(w0, w1);
                a0 = ffma2(w2, fv0p[tp], a0);
                a1 = ffma2(w2, fv1p[tp], a1);
            }
            float2 A0 = *(float2*)&a0, A1 = *(float2*)&a1;
            s_ao[r0*64 + s] = A0.x + A0.y;
            s_ao[r1*64 + s] = A1.x + A1.y;
        }
    }
    __syncthreads();

    {
        int t = tid & 63, og = tid >> 6;
        const float* xres = g_xT + (size_t)(n*V_ + v)*PLANE + 48*64;
        float*       outp = g_sR + (size_t)(n*V_ + v)*PLANE + 48*64;
        int half = t >> 5;
        #pragma unroll
        for (int i = 0; i < 4; i++) {
            int o = og*4 + i;
            float acc = __ldg(&ab[o]);
            #pragma unroll
            for (int c = 0; c < 16; c++) acc += __ldg(&aw[o*16 + c]) * s_ao[c*64 + t];
            float res = acc + xres[o*64 + t];
            outp[o*64 + t] = res;
            float vsum = res;
            #pragma unroll
            for (int off = 16; off > 0; off >>= 1)
                vsum += __shfl_down_sync(0xffffffffu, vsum, off);
            if ((t & 31) == 0) s_scr[o*2 + half] = vsum;
        }
    }
    __syncthreads();
    if (tid < 16)
        g_part[(size_t)(n*V_ + v)*64 + 48 + tid] = s_scr[2*tid] + s_scr[2*tid+1];
}

// ---------------- K2: TCN via tf32 mma.sync, persistent 148 blocks ----------------
// D[o=48][t=64] = W[48x576] @ B[576x64], B[k*64+c][t] = Xh[t+k][c] (im2col-free).
// Ws stride 580 and Xh stride 68 are ≡4 (mod 32) -> conflict-free fragment loads.
// smem floats: Ws 48*580=27840 | Xh 72*68=4896 | scr 48*4=192 -> 32928 (131712 B)
#define TCN_THREADS 384
#define TCN_SMEM_BYTES ((size_t)32928*4)
#define TCN_GRID 148
__global__ __launch_bounds__(TCN_THREADS, 1)
void k_tcn(const float* __restrict__ tb, const float* __restrict__ tbg,
           const float* __restrict__ tbb) {
    extern __shared__ float smr[];
    uint32_t* Wsu = (uint32_t*)smr;        // 27840 words
    float*    Xh  = smr + 27840;           // 72 x 68
    float*    scr = smr + 32736;           // 48 x 4
    int tid = threadIdx.x, lane = tid & 31, wid = tid >> 5;
    int g = lane >> 2, q = lane & 3;
    int m = wid % 3, ng = wid / 3;         // 3 M-tiles x 4 N-groups

    // stage W once (tf32 bits, layout [o][kc] with row stride 580)
    for (int i = tid; i < 48*576; i += TCN_THREADS) {
        int o = i / 576, kc = i - o*576;
        Wsu[o*580 + kc] = __float_as_uint(g_wTm[i]);
    }
    // zero halo rows (0..3 and 68..71)
    for (int i = tid; i < 8*68; i += TCN_THREADS) {
        int r = i / 68, cc = i - r*68;
        int rr = (r < 4) ? r : 64 + r;
        Xh[rr*68 + cc] = 0.f;
    }
    // per-thread BN constants (o rows fixed across planes)
    int o0 = m*16 + g, o1 = o0 + 8;
    float rsq = rsqrtf(1.f + EPS_);
    float ts0 = __ldg(&tbg[o0]) * rsq, ts1 = __ldg(&tbg[o1]) * rsq;
    float cb0 = __ldg(&tb[o0]) * ts0 + __ldg(&tbb[o0]);
    float cb1 = __ldg(&tb[o1]) * ts1 + __ldg(&tbb[o1]);

    const uint32_t* Ap = Wsu + o0*580 + q;         // A frags: +s*8 (+4), row+8 = +4640
    const float*    Bp = Xh + (ng*16 + g)*68 + q;  // B frags: +k*68 + cb*8 (+4), nt -> +544

    for (int p = blockIdx.x; p < NV; p += TCN_GRID) {
        // stage Xh rows 4..67 (raw fp32; mma truncates, residual re-read exact)
        const float4* xp4 = (const float4*)(g_xT + (size_t)p*PLANE);
        for (int i4 = tid; i4 < 1024; i4 += TCN_THREADS) {
            float4 qv = xp4[i4];
            int c = i4 >> 4, t0 = (i4 & 15) << 2;
            float* col = Xh + c;
            col[(t0+4)*68] = qv.x;
            col[(t0+5)*68] = qv.y;
            col[(t0+6)*68] = qv.z;
            col[(t0+7)*68] = qv.w;
        }
        __syncthreads();

        float d0[4] = {0.f,0.f,0.f,0.f}, d1[4] = {0.f,0.f,0.f,0.f};
        for (int k = 0; k < 9; k++) {
            const float* bk = Bp + k*68;
            #pragma unroll
            for (int cbk = 0; cbk < 8; cbk++) {
                int sa = (k*8 + cbk)*8;
                uint32_t a0 = Ap[sa],     a1 = Ap[4640 + sa];
                uint32_t a2 = Ap[sa + 4], a3 = Ap[4640 + sa + 4];
                const float* bb = bk + cbk*8;
                uint32_t b00 = __float_as_uint(bb[0]);
                uint32_t b01 = __float_as_uint(bb[4]);
                uint32_t b10 = __float_as_uint(bb[544]);
                uint32_t b11 = __float_as_uint(bb[548]);
                mma8(d0, a0, a1, a2, a3, b00, b01);
                mma8(d1, a0, a1, a2, a3, b10, b11);
            }
        }

        // epilogue: BN + residual + store + SE partials
        {
            const float* xr = g_xT + (size_t)p*PLANE;
            float* outp = g_sR + (size_t)p*PLANE;
            float s0 = 0.f, s1 = 0.f;
            #pragma unroll
            for (int nt = 0; nt < 2; nt++) {
                const float* dd = nt ? d1 : d0;
                int t0 = ng*16 + nt*8 + 2*q;
                float v00 = dd[0]*ts0 + cb0 + __ldg(&xr[o0*64 + t0]);
                float v01 = dd[1]*ts0 + cb0 + __ldg(&xr[o0*64 + t0 + 1]);
                float v10 = dd[2]*ts1 + cb1 + __ldg(&xr[o1*64 + t0]);
                float v11 = dd[3]*ts1 + cb1 + __ldg(&xr[o1*64 + t0 + 1]);
                *(float2*)&outp[o0*64 + t0] = make_float2(v00, v01);
                *(float2*)&outp[o1*64 + t0] = make_float2(v10, v11);
                s0 += v00 + v01;
                s1 += v10 + v11;
            }
            s0 += __shfl_down_sync(0xffffffffu, s0, 2, 4);
            s0 += __shfl_down_sync(0xffffffffu, s0, 1, 4);
            s1 += __shfl_down_sync(0xffffffffu, s1, 2, 4);
            s1 += __shfl_down_sync(0xffffffffu, s1, 1, 4);
            if (q == 0) { scr[o0*4 + ng] = s0; scr[o1*4 + ng] = s1; }
        }
        __syncthreads();
        if (tid < 48)
            g_part[(size_t)p*64 + tid] =
                scr[tid*4] + scr[tid*4+1] + scr[tid*4+2] + scr[tid*4+3];
    }
}

// ---------------- K3: SE gate MLP from partials, one block per n ----------------
__global__ void k_se(const float* __restrict__ f1w, const float* __restrict__ f1b,
                     const float* __restrict__ f2w, const float* __restrict__ f2b,
                     const float* __restrict__ bng) {
    __shared__ float s_red[4][64];
    __shared__ float s_se[64];
    __shared__ float s_h1[32];
    int n = blockIdx.x, tid = threadIdx.x;
    int c = tid & 63, vg = tid >> 6;
    float s = 0.f;
    for (int v = vg; v < V_; v += 4) s += g_part[(size_t)(n*V_ + v)*64 + c];
    s_red[vg][c] = s;
    __syncthreads();
    if (tid < 64) {
        s_se[tid] = (s_red[0][tid] + s_red[1][tid] + s_red[2][tid] + s_red[3][tid])
                    * (1.f/1600.f);
    }
    __syncthreads();
    if (tid < 32) {
        float a = f1b[tid];
        #pragma unroll
        for (int j = 0; j < 64; j++) a += f1w[tid*64 + j] * s_se[j];
        s_h1[tid] = fmaxf(a, 0.f);
    }
    __syncthreads();
    if (tid < 64) {
        float a = f2b[tid];
        #pragma unroll
        for (int j = 0; j < 32; j++) a += f2w[tid*32 + j] * s_h1[j];
        float sg = __fdividef(1.f, 1.f + __expf(-a));
        g_gmul[n*64 + tid] = (1.f + sg) * bng[tid] * rsqrtf(1.f + EPS_);
    }
}

// ---------------- K4: gate * BN * ReLU + transpose back to (N,C,T,V) ----------------
__global__ void k_final(const float* __restrict__ bnb, float* __restrict__ out) {
    __shared__ float s_buf[25*65];
    int b = blockIdx.x;
    int n = b >> 6, c = b & 63;
    const float* base = g_sR + (size_t)n*V_*PLANE + c*T_;
    for (int idx = threadIdx.x; idx < T_*V_; idx += 256) {
        int v = idx >> 6, t = idx & 63;
        s_buf[v*65 + t] = base[(size_t)v*PLANE + t];
    }
    __syncthreads();
    float m = g_gmul[n*64 + c], bb = bnb[c];
    float* op = out + (size_t)(n*64 + c)*(T_*V_);
    for (int idx = threadIdx.x; idx < T_*V_; idx += 256) {
        int t = idx / 25, v = idx - t*25;
        float val = s_buf[v*65 + t] * m + bb;
        op[idx] = fmaxf(val, 0.f);
    }
}

// ---------------- launcher: fork tcn onto side stream, overlap with attn ----------------
extern "C" void kernel_launch(void* const* d_in, const int* in_sizes, int n_in,
                              void* d_out, int out_size) {
    (void)in_sizes; (void)n_in; (void)out_size;
    const float* x    = (const float*)d_in[0];
    const float* pe   = (const float*)d_in[1];
    const float* dbg  = (const float*)d_in[2];
    const float* dbb  = (const float*)d_in[3];
    const float* qkvw = (const float*)d_in[4];
    const float* qkvb = (const float*)d_in[5];
    const float* aw   = (const float*)d_in[6];
    const float* ab   = (const float*)d_in[7];
    const float* tw   = (const float*)d_in[8];
    const float* tb   = (const float*)d_in[9];
    const float* tbg  = (const float*)d_in[10];
    const float* tbb  = (const float*)d_in[11];
    const float* f1w  = (const float*)d_in[12];
    const float* f1b  = (const float*)d_in[13];
    const float* f2w  = (const float*)d_in[14];
    const float* f2b  = (const float*)d_in[15];
    const float* bng  = (const float*)d_in[16];
    const float* bnb  = (const float*)d_in[17];

    cudaFuncSetAttribute(k_attn, cudaFuncAttributeMaxDynamicSharedMemorySize, (int)ATTN_SMEM_BYTES);
    cudaFuncSetAttribute(k_tcn,  cudaFuncAttributeMaxDynamicSharedMemorySize, (int)TCN_SMEM_BYTES);

    cudaStream_t s2;
    cudaStreamCreateWithFlags(&s2, cudaStreamNonBlocking);
    cudaEvent_t e1, e2;
    cudaEventCreateWithFlags(&e1, cudaEventDisableTiming);
    cudaEventCreateWithFlags(&e2, cudaEventDisableTiming);

    k_transpose<<<N_B*C_ + 48, 256>>>(x, tw);
    cudaEventRecord(e1, 0);
    cudaStreamWaitEvent(s2, e1, 0);
    k_tcn<<<TCN_GRID, TCN_THREADS, TCN_SMEM_BYTES, s2>>>(tb, tbg, tbb);
    k_peproj<<<V_, 256>>>(pe, qkvw, qkvb);
    k_attn<<<NV, 256, ATTN_SMEM_BYTES>>>(dbg, dbb, qkvw, qkvb, aw, ab);
    cudaEventRecord(e2, s2);
    cudaStreamWaitEvent(0, e2, 0);
    k_se<<<N_B, 256>>>(f1w, f1b, f2w, f2b, bng);
    k_final<<<N_B*C_, 256>>>(bnb, (float*)d_out);
}